// round 1
// baseline (speedup 1.0000x reference)
#include <cuda_runtime.h>
#include <math.h>

// Problem dims
#define Bq 8
#define Tq 1024
#define Cq 768
#define Hq 12
#define Dq 64

// Scratch (device globals: allocation-free rule)
__device__ float g_qkv[(size_t)Bq * Tq * 3 * Cq];   // [B*T][2304]
__device__ float g_q[(size_t)Bq * Hq * Tq * Dq];    // [B][H][T][D]
__device__ float g_k[(size_t)Bq * Hq * Tq * Dq];
__device__ float g_v[(size_t)Bq * Hq * Tq * Dq];
__device__ float g_att[(size_t)Bq * Tq * Cq];       // [B][T][C]

// ---------------------------------------------------------------------------
// Generic C[m][n] = sum_k A[m*K+k] * W[n*K+k]   (both operands K-major)
// BM=128, BN=64, BK=16, 256 threads, 8x4 micro-tile per thread.
// ---------------------------------------------------------------------------
__global__ __launch_bounds__(256) void gemm_nt(const float* __restrict__ A,
                                               const float* __restrict__ W,
                                               float* __restrict__ C,
                                               int M, int N, int K)
{
    __shared__ float As[16 * 132];  // [k][m], padded stride 132
    __shared__ float Bs[16 * 68];   // [k][n], padded stride 68

    const int tid = threadIdx.x;
    const int tx = tid & 15;        // n group
    const int ty = tid >> 4;        // m group
    const int bm = blockIdx.y * 128;
    const int bn = blockIdx.x * 64;

    float acc[8][4];
#pragma unroll
    for (int i = 0; i < 8; ++i)
#pragma unroll
        for (int j = 0; j < 4; ++j) acc[i][j] = 0.0f;

    for (int kt = 0; kt < K; kt += 16) {
        // Load A tile: 128 rows x 16 k = 512 float4, 2 per thread, store transposed
#pragma unroll
        for (int r = 0; r < 2; ++r) {
            int f = tid + r * 256;
            int row = f >> 2;
            int kv = f & 3;
            float4 a = *(const float4*)(A + (size_t)(bm + row) * K + kt + kv * 4);
            As[(kv * 4 + 0) * 132 + row] = a.x;
            As[(kv * 4 + 1) * 132 + row] = a.y;
            As[(kv * 4 + 2) * 132 + row] = a.z;
            As[(kv * 4 + 3) * 132 + row] = a.w;
        }
        // Load B tile: 64 rows x 16 k = 256 float4, 1 per thread, store transposed
        {
            int n = tid >> 2;
            int kv = tid & 3;
            float4 w = *(const float4*)(W + (size_t)(bn + n) * K + kt + kv * 4);
            Bs[(kv * 4 + 0) * 68 + n] = w.x;
            Bs[(kv * 4 + 1) * 68 + n] = w.y;
            Bs[(kv * 4 + 2) * 68 + n] = w.z;
            Bs[(kv * 4 + 3) * 68 + n] = w.w;
        }
        __syncthreads();

#pragma unroll
        for (int k = 0; k < 16; ++k) {
            float4 a0 = *(const float4*)(As + k * 132 + ty * 8);
            float4 a1 = *(const float4*)(As + k * 132 + ty * 8 + 4);
            float4 bf = *(const float4*)(Bs + k * 68 + tx * 4);
            float av[8] = {a0.x, a0.y, a0.z, a0.w, a1.x, a1.y, a1.z, a1.w};
            float bv[4] = {bf.x, bf.y, bf.z, bf.w};
#pragma unroll
            for (int i = 0; i < 8; ++i)
#pragma unroll
                for (int j = 0; j < 4; ++j)
                    acc[i][j] += av[i] * bv[j];
        }
        __syncthreads();
    }

#pragma unroll
    for (int i = 0; i < 8; ++i) {
        float4 r = make_float4(acc[i][0], acc[i][1], acc[i][2], acc[i][3]);
        *(float4*)(C + (size_t)(bm + ty * 8 + i) * N + bn + tx * 4) = r;
    }
}

// ---------------------------------------------------------------------------
// RoPE + scatter: g_qkv [B*T][2304] -> g_q/g_k/g_v [B][H][T][D], rope on q,k.
// One thread per (b,t,h,i) with i in [0,32): handles pair (d=i, d=i+32).
// ---------------------------------------------------------------------------
__global__ __launch_bounds__(256) void rope_scatter()
{
    int gid = blockIdx.x * 256 + threadIdx.x;          // [0, B*T*H*32)
    int i = gid & 31;
    int h = (gid >> 5) % Hq;
    int bt = gid / (32 * Hq);
    int t = bt & (Tq - 1);
    int b = bt >> 10;

    const float* row = g_qkv + (size_t)bt * (3 * Cq);

    // inv_freq = 10000^(-i/32) = 2^(-i*log2(10000)/32)
    float ang = (float)t * exp2f(-(float)i * (13.2877123795494936f / 32.0f));
    float s, c;
    sincosf(ang, &s, &c);

    int base = h * 64;
    size_t dst = ((size_t)(b * Hq + h) * Tq + t) * 64;

    // q
    {
        float x1 = row[base + i];
        float x2 = row[base + i + 32];
        g_q[dst + i]      = x1 * c + x2 * s;
        g_q[dst + i + 32] = -x1 * s + x2 * c;
    }
    // k
    {
        float x1 = row[Cq + base + i];
        float x2 = row[Cq + base + i + 32];
        g_k[dst + i]      = x1 * c + x2 * s;
        g_k[dst + i + 32] = -x1 * s + x2 * c;
    }
    // v (plain copy)
    {
        g_v[dst + i]      = row[2 * Cq + base + i];
        g_v[dst + i + 32] = row[2 * Cq + base + i + 32];
    }
}

// ---------------------------------------------------------------------------
// Flash attention (causal), fp32. One block = (b, h, 64-query tile).
// 256 threads. Score & PV phases each use 4x4 micro-tiles per thread.
// Dynamic smem layout (floats):
//   Qs [64][68]  (d-major, padded)   17408 B
//   Ks [64][68]  (d-major, padded)   17408 B
//   Vs [64][64]  (s-major)           16384 B
//   Ss [64][64]  (q-major)           16384 B
//   smax/ssum/scorr [64] each          768 B
// total 68352 B  -> needs MaxDynamicSharedMemorySize attribute.
// ---------------------------------------------------------------------------
#define ATTN_SMEM_BYTES ((64 * 68 * 2 + 64 * 64 * 2 + 3 * 64) * 4)

__global__ __launch_bounds__(256) void attn_kernel(const float* __restrict__ gq,
                                                   const float* __restrict__ gk,
                                                   const float* __restrict__ gv,
                                                   float* __restrict__ gatt)
{
    extern __shared__ float sm[];
    float* Qs = sm;                  // [d][q] stride 68
    float* Ks = Qs + 64 * 68;        // [d][s] stride 68
    float* Vs = Ks + 64 * 68;        // [s][d] stride 64
    float* Ss = Vs + 64 * 64;        // [q][s] stride 64
    float* smax  = Ss + 64 * 64;
    float* ssum  = smax + 64;
    float* scorr = ssum + 64;

    const int tid = threadIdx.x;
    const int tx = tid & 15;         // s-group / d-group
    const int ty = tid >> 4;         // q-group
    const int qb = blockIdx.x;
    const int h = blockIdx.y;
    const int b = blockIdx.z;

    const float* qp = gq + ((size_t)(b * Hq + h) * Tq + qb * 64) * 64;
    const float* kp = gk + (size_t)(b * Hq + h) * Tq * 64;
    const float* vp = gv + (size_t)(b * Hq + h) * Tq * 64;

    // Load Q tile transposed into Qs[d][q]
#pragma unroll
    for (int r = 0; r < 4; ++r) {
        int f = tid + r * 256;
        int row = f >> 4;            // q row 0..63
        int dv = f & 15;             // d float4 index
        float4 qv = *(const float4*)(qp + row * 64 + dv * 4);
        Qs[(dv * 4 + 0) * 68 + row] = qv.x;
        Qs[(dv * 4 + 1) * 68 + row] = qv.y;
        Qs[(dv * 4 + 2) * 68 + row] = qv.z;
        Qs[(dv * 4 + 3) * 68 + row] = qv.w;
    }
    if (tid < 64) { smax[tid] = -1e30f; ssum[tid] = 0.0f; }

    float o[4][4];
#pragma unroll
    for (int i = 0; i < 4; ++i)
#pragma unroll
        for (int j = 0; j < 4; ++j) o[i][j] = 0.0f;

    __syncthreads();

    for (int st = 0; st <= qb; ++st) {
        // Load K (transposed) and V tiles
        const float* kt = kp + (size_t)st * 64 * 64;
        const float* vt = vp + (size_t)st * 64 * 64;
#pragma unroll
        for (int r = 0; r < 4; ++r) {
            int f = tid + r * 256;
            int row = f >> 4;        // s row 0..63
            int dv = f & 15;
            float4 kv4 = *(const float4*)(kt + row * 64 + dv * 4);
            Ks[(dv * 4 + 0) * 68 + row] = kv4.x;
            Ks[(dv * 4 + 1) * 68 + row] = kv4.y;
            Ks[(dv * 4 + 2) * 68 + row] = kv4.z;
            Ks[(dv * 4 + 3) * 68 + row] = kv4.w;
            float4 vv4 = *(const float4*)(vt + row * 64 + dv * 4);
            *(float4*)(Vs + row * 64 + dv * 4) = vv4;
        }
        __syncthreads();

        // Scores S[q][s] = sum_d Q[q][d]*K[s][d]
        float s[4][4];
#pragma unroll
        for (int i = 0; i < 4; ++i)
#pragma unroll
            for (int j = 0; j < 4; ++j) s[i][j] = 0.0f;

#pragma unroll 8
        for (int d = 0; d < 64; ++d) {
            float qf[4];
#pragma unroll
            for (int i = 0; i < 4; ++i) qf[i] = Qs[d * 68 + ty * 4 + i];
            float4 kf = *(const float4*)(Ks + d * 68 + tx * 4);
            float kv[4] = {kf.x, kf.y, kf.z, kf.w};
#pragma unroll
            for (int i = 0; i < 4; ++i)
#pragma unroll
                for (int j = 0; j < 4; ++j)
                    s[i][j] += qf[i] * kv[j];
        }

        // Scale + causal mask, store to Ss[q][s]
        const bool diag = (st == qb);
#pragma unroll
        for (int i = 0; i < 4; ++i) {
            float v0 = s[i][0] * 0.125f;
            float v1 = s[i][1] * 0.125f;
            float v2 = s[i][2] * 0.125f;
            float v3 = s[i][3] * 0.125f;
            if (diag) {
                int qg = ty * 4 + i;
                if (tx * 4 + 0 > qg) v0 = -1e30f;
                if (tx * 4 + 1 > qg) v1 = -1e30f;
                if (tx * 4 + 2 > qg) v2 = -1e30f;
                if (tx * 4 + 3 > qg) v3 = -1e30f;
            }
            *(float4*)(Ss + (ty * 4 + i) * 64 + tx * 4) = make_float4(v0, v1, v2, v3);
        }
        __syncthreads();

        // Online softmax: 4 threads per query row, 16 keys each
        {
            int qq = tid >> 2;
            int g = tid & 3;
            float* row = Ss + qq * 64 + g * 16;
            float mx = row[0];
#pragma unroll
            for (int u = 1; u < 16; ++u) mx = fmaxf(mx, row[u]);
            mx = fmaxf(mx, __shfl_xor_sync(0xffffffffu, mx, 1));
            mx = fmaxf(mx, __shfl_xor_sync(0xffffffffu, mx, 2));
            float m_old = smax[qq];
            float m_new = fmaxf(m_old, mx);
            float sum = 0.0f;
#pragma unroll
            for (int u = 0; u < 16; ++u) {
                float p = __expf(row[u] - m_new);
                row[u] = p;
                sum += p;
            }
            sum += __shfl_xor_sync(0xffffffffu, sum, 1);
            sum += __shfl_xor_sync(0xffffffffu, sum, 2);
            if (g == 0) {
                float corr = __expf(m_old - m_new);
                scorr[qq] = corr;
                smax[qq] = m_new;
                ssum[qq] = ssum[qq] * corr + sum;
            }
        }
        __syncthreads();

        // O = O*corr + P @ V
        float cr[4];
#pragma unroll
        for (int i = 0; i < 4; ++i) cr[i] = scorr[ty * 4 + i];
#pragma unroll
        for (int i = 0; i < 4; ++i)
#pragma unroll
            for (int j = 0; j < 4; ++j) o[i][j] *= cr[i];

#pragma unroll 8
        for (int s2 = 0; s2 < 64; ++s2) {
            float pf[4];
#pragma unroll
            for (int i = 0; i < 4; ++i) pf[i] = Ss[(ty * 4 + i) * 64 + s2];
            float4 vf = *(const float4*)(Vs + s2 * 64 + tx * 4);
            float vv[4] = {vf.x, vf.y, vf.z, vf.w};
#pragma unroll
            for (int i = 0; i < 4; ++i)
#pragma unroll
                for (int j = 0; j < 4; ++j)
                    o[i][j] += pf[i] * vv[j];
        }
        __syncthreads();  // before next tile overwrites Ks/Vs/Ss
    }

    // Finalize and write to g_att [B][T][C]
#pragma unroll
    for (int i = 0; i < 4; ++i) {
        int qq = ty * 4 + i;
        float linv = 1.0f / ssum[qq];
        int t = qb * 64 + qq;
        float4 r = make_float4(o[i][0] * linv, o[i][1] * linv,
                               o[i][2] * linv, o[i][3] * linv);
        *(float4*)(gatt + ((size_t)b * Tq + t) * Cq + h * 64 + tx * 4) = r;
    }
}

// ---------------------------------------------------------------------------
// Launch
// ---------------------------------------------------------------------------
extern "C" void kernel_launch(void* const* d_in, const int* in_sizes, int n_in,
                              void* d_out, int out_size)
{
    const float* x      = (const float*)d_in[0];
    const float* w_qkv  = (const float*)d_in[1];
    const float* w_proj = (const float*)d_in[2];
    float* out = (float*)d_out;

    float *qkv, *q, *k, *v, *att;
    cudaGetSymbolAddress((void**)&qkv, g_qkv);
    cudaGetSymbolAddress((void**)&q, g_q);
    cudaGetSymbolAddress((void**)&k, g_k);
    cudaGetSymbolAddress((void**)&v, g_v);
    cudaGetSymbolAddress((void**)&att, g_att);

    const int M = Bq * Tq;  // 8192

    // 1. qkv = x @ w_qkv^T   [8192 x 2304]
    gemm_nt<<<dim3((3 * Cq) / 64, M / 128), 256>>>(x, w_qkv, qkv, M, 3 * Cq, Cq);

    // 2. RoPE + scatter to [B][H][T][D]
    rope_scatter<<<(Bq * Tq * Hq * 32) / 256, 256>>>();

    // 3. Causal flash attention -> g_att [B][T][C]
    cudaFuncSetAttribute(attn_kernel, cudaFuncAttributeMaxDynamicSharedMemorySize,
                         ATTN_SMEM_BYTES);
    attn_kernel<<<dim3(Tq / 64, Hq, Bq), 256, ATTN_SMEM_BYTES>>>(q, k, v, att);

    // 4. out = att @ w_proj^T  [8192 x 768]
    gemm_nt<<<dim3(Cq / 64, M / 128), 256>>>(att, w_proj, out, M, Cq, Cq);
}

// round 7
// speedup vs baseline: 1.6976x; 1.6976x over previous
#include <cuda_runtime.h>
#include <math.h>
#include <cstdint>

// Problem dims
#define Bq 8
#define Tq 1024
#define Cq 768
#define Hq 12
#define Dq 64

// Scratch (device globals: allocation-free rule)
__device__ float g_qkv[(size_t)Bq * Tq * 3 * Cq];   // [B*T][2304]
__device__ float g_q[(size_t)Bq * Hq * Tq * Dq];    // [B][H][T][D]
__device__ float g_k[(size_t)Bq * Hq * Tq * Dq];
__device__ float g_v[(size_t)Bq * Hq * Tq * Dq];
__device__ float g_att[(size_t)Bq * Tq * Cq];       // [B][T][C]

// ---------------------------------------------------------------------------
// Helpers
// ---------------------------------------------------------------------------
__device__ __forceinline__ uint32_t smem_u32(const void* p) {
    uint32_t a;
    asm("{ .reg .u64 t; cvta.to.shared.u64 t, %1; cvt.u32.u64 %0, t; }"
        : "=r"(a) : "l"(p));
    return a;
}

__device__ __forceinline__ uint32_t cvt_tf32(float v) {
    uint32_t u;
    asm("cvt.rna.tf32.f32 %0, %1;" : "=r"(u) : "f"(v));
    return u;
}

__device__ __forceinline__ void mma_tf32(float* d, const uint32_t* a,
                                         const uint32_t* b) {
    asm volatile(
        "mma.sync.aligned.m16n8k8.row.col.f32.tf32.tf32.f32 "
        "{%0,%1,%2,%3}, {%4,%5,%6,%7}, {%8,%9}, {%0,%1,%2,%3};"
        : "+f"(d[0]), "+f"(d[1]), "+f"(d[2]), "+f"(d[3])
        : "r"(a[0]), "r"(a[1]), "r"(a[2]), "r"(a[3]), "r"(b[0]), "r"(b[1]));
}

// Swizzled smem read: tile stored row-major [row][32] floats, 16B chunks
// XORed by (row&7). Conflict-free for fragment loads.
__device__ __forceinline__ float lds_sw(const float* base, int row, int k) {
    return base[row * 32 + (((k >> 2) ^ (row & 7)) << 2) + (k & 3)];
}

// ---------------------------------------------------------------------------
// tf32 mma.sync GEMM: C[m][n] = sum_k A[m*K+k] * W[n*K+k]
// BM=128, BN=128, BK=32, 256 threads (8 warps, 2x4 grid, warp tile 64x32).
// Requires M%128==0, N%128==0, K%32==0.
// ---------------------------------------------------------------------------
#define GEMM_SMEM_BYTES (4 * 16384)   // A0,A1,B0,B1

__global__ __launch_bounds__(256)
void gemm_tf32(const float* __restrict__ A, const float* __restrict__ W,
               float* __restrict__ C, int M, int N, int K)
{
    extern __shared__ float sm[];
    const uint32_t sb = smem_u32(sm);

    const int tid = threadIdx.x;
    const int wid = tid >> 5;
    const int lane = tid & 31;
    const int wm = wid & 1;          // warp m index (0..1)
    const int wn = wid >> 1;         // warp n index (0..3)
    const int bm = blockIdx.y * 128;
    const int bn = blockIdx.x * 128;
    const int nK = K >> 5;

    const int c4 = tid & 7;          // float4 column in 128B row
    const int r0 = tid >> 3;         // 0..31
    const float* Ag = A + (size_t)(bm + r0) * K + c4 * 4;
    const float* Wg = W + (size_t)(bn + r0) * K + c4 * 4;

    float acc[4][4][4];
#pragma unroll
    for (int mi = 0; mi < 4; ++mi)
#pragma unroll
        for (int ni = 0; ni < 4; ++ni)
#pragma unroll
            for (int j = 0; j < 4; ++j) acc[mi][ni][j] = 0.0f;

    // ---- prologue: load tile 0 into buffer 0 ----
    {
        uint32_t sa = sb;                  // A buf 0
        uint32_t sw = sb + 32768;          // B buf 0
#pragma unroll
        for (int i = 0; i < 4; ++i) {
            int row = r0 + i * 32;
            uint32_t off = row * 128 + ((c4 ^ (row & 7)) << 4);
            asm volatile("cp.async.cg.shared.global [%0], [%1], 16;"
                         :: "r"(sa + off), "l"(Ag + (size_t)i * 32 * K) : "memory");
            asm volatile("cp.async.cg.shared.global [%0], [%1], 16;"
                         :: "r"(sw + off), "l"(Wg + (size_t)i * 32 * K) : "memory");
        }
        asm volatile("cp.async.commit_group;" ::: "memory");
    }

    for (int kt = 0; kt < nK; ++kt) {
        if (kt + 1 < nK) {
            int nb = (kt + 1) & 1;
            uint32_t sa = sb + nb * 16384;
            uint32_t sw = sb + 32768 + nb * 16384;
            const float* ag = Ag + (size_t)(kt + 1) * 32;
            const float* wg = Wg + (size_t)(kt + 1) * 32;
#pragma unroll
            for (int i = 0; i < 4; ++i) {
                int row = r0 + i * 32;
                uint32_t off = row * 128 + ((c4 ^ (row & 7)) << 4);
                asm volatile("cp.async.cg.shared.global [%0], [%1], 16;"
                             :: "r"(sa + off), "l"(ag + (size_t)i * 32 * K) : "memory");
                asm volatile("cp.async.cg.shared.global [%0], [%1], 16;"
                             :: "r"(sw + off), "l"(wg + (size_t)i * 32 * K) : "memory");
            }
            asm volatile("cp.async.commit_group;" ::: "memory");
            asm volatile("cp.async.wait_group 1;" ::: "memory");
        } else {
            asm volatile("cp.async.wait_group 0;" ::: "memory");
        }
        __syncthreads();

        const int buf = kt & 1;
        const float* a = sm + buf * 4096;
        const float* b = sm + 8192 + buf * 4096;

#pragma unroll
        for (int ks = 0; ks < 4; ++ks) {
            const int k0 = ks * 8 + (lane & 3);
            const int k1 = k0 + 4;

            uint32_t af[4][4];
#pragma unroll
            for (int mi = 0; mi < 4; ++mi) {
                int r1 = wm * 64 + mi * 16 + (lane >> 2);
                int r2 = r1 + 8;
                af[mi][0] = cvt_tf32(lds_sw(a, r1, k0));
                af[mi][1] = cvt_tf32(lds_sw(a, r2, k0));
                af[mi][2] = cvt_tf32(lds_sw(a, r1, k1));
                af[mi][3] = cvt_tf32(lds_sw(a, r2, k1));
            }
            uint32_t bf[4][2];
#pragma unroll
            for (int ni = 0; ni < 4; ++ni) {
                int n = wn * 32 + ni * 8 + (lane >> 2);
                bf[ni][0] = cvt_tf32(lds_sw(b, n, k0));
                bf[ni][1] = cvt_tf32(lds_sw(b, n, k1));
            }
#pragma unroll
            for (int mi = 0; mi < 4; ++mi)
#pragma unroll
                for (int ni = 0; ni < 4; ++ni)
                    mma_tf32(acc[mi][ni], af[mi], bf[ni]);
        }
        __syncthreads();
    }

    // Epilogue: direct float2 stores
#pragma unroll
    for (int mi = 0; mi < 4; ++mi) {
        int r1 = bm + wm * 64 + mi * 16 + (lane >> 2);
#pragma unroll
        for (int ni = 0; ni < 4; ++ni) {
            int cc = bn + wn * 32 + ni * 8 + (lane & 3) * 2;
            *(float2*)(C + (size_t)r1 * N + cc) =
                make_float2(acc[mi][ni][0], acc[mi][ni][1]);
            *(float2*)(C + (size_t)(r1 + 8) * N + cc) =
                make_float2(acc[mi][ni][2], acc[mi][ni][3]);
        }
    }
}

// ---------------------------------------------------------------------------
// RoPE + scatter: g_qkv [B*T][2304] -> g_q/g_k/g_v [B][H][T][D], rope on q,k.
// ---------------------------------------------------------------------------
__global__ __launch_bounds__(256) void rope_scatter()
{
    int gid = blockIdx.x * 256 + threadIdx.x;          // [0, B*T*H*32)
    int i = gid & 31;
    int h = (gid >> 5) % Hq;
    int bt = gid / (32 * Hq);
    int t = bt & (Tq - 1);
    int b = bt >> 10;

    const float* row = g_qkv + (size_t)bt * (3 * Cq);

    float ang = (float)t * exp2f(-(float)i * (13.2877123795494936f / 32.0f));
    float s, c;
    sincosf(ang, &s, &c);

    int base = h * 64;
    size_t dst = ((size_t)(b * Hq + h) * Tq + t) * 64;

    {
        float x1 = row[base + i];
        float x2 = row[base + i + 32];
        g_q[dst + i]      = x1 * c + x2 * s;
        g_q[dst + i + 32] = -x1 * s + x2 * c;
    }
    {
        float x1 = row[Cq + base + i];
        float x2 = row[Cq + base + i + 32];
        g_k[dst + i]      = x1 * c + x2 * s;
        g_k[dst + i + 32] = -x1 * s + x2 * c;
    }
    {
        g_v[dst + i]      = row[2 * Cq + base + i];
        g_v[dst + i + 32] = row[2 * Cq + base + i + 32];
    }
}

// ---------------------------------------------------------------------------
// Flash attention (causal), fp32 SIMT. One block = (b, h, 64-query tile).
// ---------------------------------------------------------------------------
#define ATTN_SMEM_BYTES ((64 * 68 * 2 + 64 * 64 * 2 + 3 * 64) * 4)

__global__ __launch_bounds__(256) void attn_kernel(const float* __restrict__ gq,
                                                   const float* __restrict__ gk,
                                                   const float* __restrict__ gv,
                                                   float* __restrict__ gatt)
{
    extern __shared__ float smA[];
    float* Qs = smA;                 // [d][q] stride 68
    float* Ks = Qs + 64 * 68;        // [d][s] stride 68
    float* Vs = Ks + 64 * 68;        // [s][d] stride 64
    float* Ss = Vs + 64 * 64;        // [q][s] stride 64
    float* smax  = Ss + 64 * 64;
    float* ssum  = smax + 64;
    float* scorr = ssum + 64;

    const int tid = threadIdx.x;
    const int tx = tid & 15;
    const int ty = tid >> 4;
    const int qb = blockIdx.x;
    const int h = blockIdx.y;
    const int b = blockIdx.z;

    const float* qp = gq + ((size_t)(b * Hq + h) * Tq + qb * 64) * 64;
    const float* kp = gk + (size_t)(b * Hq + h) * Tq * 64;
    const float* vp = gv + (size_t)(b * Hq + h) * Tq * 64;

#pragma unroll
    for (int r = 0; r < 4; ++r) {
        int f = tid + r * 256;
        int row = f >> 4;
        int dv = f & 15;
        float4 qv = *(const float4*)(qp + row * 64 + dv * 4);
        Qs[(dv * 4 + 0) * 68 + row] = qv.x;
        Qs[(dv * 4 + 1) * 68 + row] = qv.y;
        Qs[(dv * 4 + 2) * 68 + row] = qv.z;
        Qs[(dv * 4 + 3) * 68 + row] = qv.w;
    }
    if (tid < 64) { smax[tid] = -1e30f; ssum[tid] = 0.0f; }

    float o[4][4];
#pragma unroll
    for (int i = 0; i < 4; ++i)
#pragma unroll
        for (int j = 0; j < 4; ++j) o[i][j] = 0.0f;

    __syncthreads();

    for (int st = 0; st <= qb; ++st) {
        const float* kt = kp + (size_t)st * 64 * 64;
        const float* vt = vp + (size_t)st * 64 * 64;
#pragma unroll
        for (int r = 0; r < 4; ++r) {
            int f = tid + r * 256;
            int row = f >> 4;
            int dv = f & 15;
            float4 kv4 = *(const float4*)(kt + row * 64 + dv * 4);
            Ks[(dv * 4 + 0) * 68 + row] = kv4.x;
            Ks[(dv * 4 + 1) * 68 + row] = kv4.y;
            Ks[(dv * 4 + 2) * 68 + row] = kv4.z;
            Ks[(dv * 4 + 3) * 68 + row] = kv4.w;
            float4 vv4 = *(const float4*)(vt + row * 64 + dv * 4);
            *(float4*)(Vs + row * 64 + dv * 4) = vv4;
        }
        __syncthreads();

        float s[4][4];
#pragma unroll
        for (int i = 0; i < 4; ++i)
#pragma unroll
            for (int j = 0; j < 4; ++j) s[i][j] = 0.0f;

#pragma unroll 8
        for (int d = 0; d < 64; ++d) {
            float qf[4];
#pragma unroll
            for (int i = 0; i < 4; ++i) qf[i] = Qs[d * 68 + ty * 4 + i];
            float4 kf = *(const float4*)(Ks + d * 68 + tx * 4);
            float kv[4] = {kf.x, kf.y, kf.z, kf.w};
#pragma unroll
            for (int i = 0; i < 4; ++i)
#pragma unroll
                for (int j = 0; j < 4; ++j)
                    s[i][j] += qf[i] * kv[j];
        }

        const bool diag = (st == qb);
#pragma unroll
        for (int i = 0; i < 4; ++i) {
            float v0 = s[i][0] * 0.125f;
            float v1 = s[i][1] * 0.125f;
            float v2 = s[i][2] * 0.125f;
            float v3 = s[i][3] * 0.125f;
            if (diag) {
                int qg = ty * 4 + i;
                if (tx * 4 + 0 > qg) v0 = -1e30f;
                if (tx * 4 + 1 > qg) v1 = -1e30f;
                if (tx * 4 + 2 > qg) v2 = -1e30f;
                if (tx * 4 + 3 > qg) v3 = -1e30f;
            }
            *(float4*)(Ss + (ty * 4 + i) * 64 + tx * 4) = make_float4(v0, v1, v2, v3);
        }
        __syncthreads();

        {
            int qq = tid >> 2;
            int g = tid & 3;
            float* row = Ss + qq * 64 + g * 16;
            float mx = row[0];
#pragma unroll
            for (int u = 1; u < 16; ++u) mx = fmaxf(mx, row[u]);
            mx = fmaxf(mx, __shfl_xor_sync(0xffffffffu, mx, 1));
            mx = fmaxf(mx, __shfl_xor_sync(0xffffffffu, mx, 2));
            float m_old = smax[qq];
            float m_new = fmaxf(m_old, mx);
            float sum = 0.0f;
#pragma unroll
            for (int u = 0; u < 16; ++u) {
                float p = __expf(row[u] - m_new);
                row[u] = p;
                sum += p;
            }
            sum += __shfl_xor_sync(0xffffffffu, sum, 1);
            sum += __shfl_xor_sync(0xffffffffu, sum, 2);
            if (g == 0) {
                float corr = __expf(m_old - m_new);
                scorr[qq] = corr;
                smax[qq] = m_new;
                ssum[qq] = ssum[qq] * corr + sum;
            }
        }
        __syncthreads();

        float cr[4];
#pragma unroll
        for (int i = 0; i < 4; ++i) cr[i] = scorr[ty * 4 + i];
#pragma unroll
        for (int i = 0; i < 4; ++i)
#pragma unroll
            for (int j = 0; j < 4; ++j) o[i][j] *= cr[i];

#pragma unroll 8
        for (int s2 = 0; s2 < 64; ++s2) {
            float pf[4];
#pragma unroll
            for (int i = 0; i < 4; ++i) pf[i] = Ss[(ty * 4 + i) * 64 + s2];
            float4 vf = *(const float4*)(Vs + s2 * 64 + tx * 4);
            float vv[4] = {vf.x, vf.y, vf.z, vf.w};
#pragma unroll
            for (int i = 0; i < 4; ++i)
#pragma unroll
                for (int j = 0; j < 4; ++j)
                    o[i][j] += pf[i] * vv[j];
        }
        __syncthreads();
    }

#pragma unroll
    for (int i = 0; i < 4; ++i) {
        int qq = ty * 4 + i;
        float linv = 1.0f / ssum[qq];
        int t = qb * 64 + qq;
        float4 r = make_float4(o[i][0] * linv, o[i][1] * linv,
                               o[i][2] * linv, o[i][3] * linv);
        *(float4*)(gatt + ((size_t)b * Tq + t) * Cq + h * 64 + tx * 4) = r;
    }
}

// ---------------------------------------------------------------------------
// Launch
// ---------------------------------------------------------------------------
extern "C" void kernel_launch(void* const* d_in, const int* in_sizes, int n_in,
                              void* d_out, int out_size)
{
    const float* x      = (const float*)d_in[0];
    const float* w_qkv  = (const float*)d_in[1];
    const float* w_proj = (const float*)d_in[2];
    float* out = (float*)d_out;

    float *qkv, *q, *k, *v, *att;
    cudaGetSymbolAddress((void**)&qkv, g_qkv);
    cudaGetSymbolAddress((void**)&q, g_q);
    cudaGetSymbolAddress((void**)&k, g_k);
    cudaGetSymbolAddress((void**)&v, g_v);
    cudaGetSymbolAddress((void**)&att, g_att);

    const int M = Bq * Tq;  // 8192

    cudaFuncSetAttribute(gemm_tf32, cudaFuncAttributeMaxDynamicSharedMemorySize,
                         GEMM_SMEM_BYTES);
    cudaFuncSetAttribute(attn_kernel, cudaFuncAttributeMaxDynamicSharedMemorySize,
                         ATTN_SMEM_BYTES);

    // 1. qkv = x @ w_qkv^T   [8192 x 2304]
    gemm_tf32<<<dim3((3 * Cq) / 128, M / 128), 256, GEMM_SMEM_BYTES>>>(
        x, w_qkv, qkv, M, 3 * Cq, Cq);

    // 2. RoPE + scatter to [B][H][T][D]
    rope_scatter<<<(Bq * Tq * Hq * 32) / 256, 256>>>();

    // 3. Causal flash attention -> g_att [B][T][C]
    attn_kernel<<<dim3(Tq / 64, Hq, Bq), 256, ATTN_SMEM_BYTES>>>(q, k, v, att);

    // 4. out = att @ w_proj^T  [8192 x 768]
    gemm_tf32<<<dim3(Cq / 128, M / 128), 256, GEMM_SMEM_BYTES>>>(
        att, w_proj, out, M, Cq, Cq);
}

// round 10
// speedup vs baseline: 2.9815x; 1.7563x over previous
#include <cuda_runtime.h>
#include <math.h>
#include <cstdint>

// Problem dims
#define Bq 8
#define Tq 1024
#define Cq 768
#define Hq 12
#define Dq 64

// Scratch (device globals: allocation-free rule)
__device__ float g_qkv[(size_t)Bq * Tq * 3 * Cq];   // [B*T][2304]
__device__ float g_q[(size_t)Bq * Hq * Tq * Dq];    // [B][H][T][D] (tf32-rounded)
__device__ float g_k[(size_t)Bq * Hq * Tq * Dq];
__device__ float g_v[(size_t)Bq * Hq * Tq * Dq];
__device__ float g_att[(size_t)Bq * Tq * Cq];       // [B][T][C]   (tf32-rounded)
__device__ float g_xr[(size_t)Bq * Tq * Cq];        // rounded x
__device__ float g_wqkv_r[(size_t)3 * Cq * Cq];     // rounded w_qkv
__device__ float g_wproj_r[(size_t)Cq * Cq];        // rounded w_proj

// ---------------------------------------------------------------------------
// Helpers
// ---------------------------------------------------------------------------
__device__ __forceinline__ uint32_t smem_u32(const void* p) {
    uint32_t a;
    asm("{ .reg .u64 t; cvta.to.shared.u64 t, %1; cvt.u32.u64 %0, t; }"
        : "=r"(a) : "l"(p));
    return a;
}

__device__ __forceinline__ uint32_t cvt_tf32(float v) {
    uint32_t u;
    asm("cvt.rna.tf32.f32 %0, %1;" : "=r"(u) : "f"(v));
    return u;
}

__device__ __forceinline__ void mma_tf32(float* d, const uint32_t* a,
                                         const uint32_t* b) {
    asm volatile(
        "mma.sync.aligned.m16n8k8.row.col.f32.tf32.tf32.f32 "
        "{%0,%1,%2,%3}, {%4,%5,%6,%7}, {%8,%9}, {%0,%1,%2,%3};"
        : "+f"(d[0]), "+f"(d[1]), "+f"(d[2]), "+f"(d[3])
        : "r"(a[0]), "r"(a[1]), "r"(a[2]), "r"(a[3]), "r"(b[0]), "r"(b[1]));
}

// XOR-swizzled float index: row-major [s][64], 16B chunks XORed by (s&7)
__device__ __forceinline__ int swz(int s, int d) {
    return s * 64 + ((((d >> 2) ^ (s & 7)) << 2) | (d & 3));
}

__device__ __forceinline__ float lds_sw(const float* base, int row, int k) {
    return base[row * 32 + (((k >> 2) ^ (row & 7)) << 2) + (k & 3)];
}

// ---------------------------------------------------------------------------
// Round-to-tf32 copy kernel (n divisible by 4)
// ---------------------------------------------------------------------------
__global__ __launch_bounds__(256) void round_tf32_k(const float* __restrict__ in,
                                                    float* __restrict__ out, int n4)
{
    int i = blockIdx.x * 256 + threadIdx.x;
    if (i < n4) {
        float4 v = ((const float4*)in)[i];
        v.x = __uint_as_float(cvt_tf32(v.x));
        v.y = __uint_as_float(cvt_tf32(v.y));
        v.z = __uint_as_float(cvt_tf32(v.z));
        v.w = __uint_as_float(cvt_tf32(v.w));
        ((float4*)out)[i] = v;
    }
}

// ---------------------------------------------------------------------------
// tf32 mma.sync GEMM: C[m][n] = sum_k A[m*K+k] * W[n*K+k]
// Inputs must already be tf32-rounded. BM=128, BN=128, BK=32, 256 threads.
// ---------------------------------------------------------------------------
#define GEMM_SMEM_BYTES (4 * 16384)

__global__ __launch_bounds__(256)
void gemm_tf32(const float* __restrict__ A, const float* __restrict__ W,
               float* __restrict__ C, int M, int N, int K)
{
    extern __shared__ float sm[];
    const uint32_t sb = smem_u32(sm);

    const int tid = threadIdx.x;
    const int wid = tid >> 5;
    const int lane = tid & 31;
    const int wm = wid & 1;
    const int wn = wid >> 1;
    const int bm = blockIdx.y * 128;
    const int bn = blockIdx.x * 128;
    const int nK = K >> 5;

    const int c4 = tid & 7;
    const int r0 = tid >> 3;
    const float* Ag = A + (size_t)(bm + r0) * K + c4 * 4;
    const float* Wg = W + (size_t)(bn + r0) * K + c4 * 4;

    float acc[4][4][4];
#pragma unroll
    for (int mi = 0; mi < 4; ++mi)
#pragma unroll
        for (int ni = 0; ni < 4; ++ni)
#pragma unroll
            for (int j = 0; j < 4; ++j) acc[mi][ni][j] = 0.0f;

    {
        uint32_t sa = sb;
        uint32_t sw = sb + 32768;
#pragma unroll
        for (int i = 0; i < 4; ++i) {
            int row = r0 + i * 32;
            uint32_t off = row * 128 + ((c4 ^ (row & 7)) << 4);
            asm volatile("cp.async.cg.shared.global [%0], [%1], 16;"
                         :: "r"(sa + off), "l"(Ag + (size_t)i * 32 * K) : "memory");
            asm volatile("cp.async.cg.shared.global [%0], [%1], 16;"
                         :: "r"(sw + off), "l"(Wg + (size_t)i * 32 * K) : "memory");
        }
        asm volatile("cp.async.commit_group;" ::: "memory");
    }

    for (int kt = 0; kt < nK; ++kt) {
        if (kt + 1 < nK) {
            int nb = (kt + 1) & 1;
            uint32_t sa = sb + nb * 16384;
            uint32_t sw = sb + 32768 + nb * 16384;
            const float* ag = Ag + (size_t)(kt + 1) * 32;
            const float* wg = Wg + (size_t)(kt + 1) * 32;
#pragma unroll
            for (int i = 0; i < 4; ++i) {
                int row = r0 + i * 32;
                uint32_t off = row * 128 + ((c4 ^ (row & 7)) << 4);
                asm volatile("cp.async.cg.shared.global [%0], [%1], 16;"
                             :: "r"(sa + off), "l"(ag + (size_t)i * 32 * K) : "memory");
                asm volatile("cp.async.cg.shared.global [%0], [%1], 16;"
                             :: "r"(sw + off), "l"(wg + (size_t)i * 32 * K) : "memory");
            }
            asm volatile("cp.async.commit_group;" ::: "memory");
            asm volatile("cp.async.wait_group 1;" ::: "memory");
        } else {
            asm volatile("cp.async.wait_group 0;" ::: "memory");
        }
        __syncthreads();

        const int buf = kt & 1;
        const float* a = sm + buf * 4096;
        const float* b = sm + 8192 + buf * 4096;

#pragma unroll
        for (int ks = 0; ks < 4; ++ks) {
            const int k0 = ks * 8 + (lane & 3);
            const int k1 = k0 + 4;

            uint32_t af[4][4];
#pragma unroll
            for (int mi = 0; mi < 4; ++mi) {
                int r1 = wm * 64 + mi * 16 + (lane >> 2);
                int r2 = r1 + 8;
                af[mi][0] = __float_as_uint(lds_sw(a, r1, k0));
                af[mi][1] = __float_as_uint(lds_sw(a, r2, k0));
                af[mi][2] = __float_as_uint(lds_sw(a, r1, k1));
                af[mi][3] = __float_as_uint(lds_sw(a, r2, k1));
            }
            uint32_t bf[4][2];
#pragma unroll
            for (int ni = 0; ni < 4; ++ni) {
                int n = wn * 32 + ni * 8 + (lane >> 2);
                bf[ni][0] = __float_as_uint(lds_sw(b, n, k0));
                bf[ni][1] = __float_as_uint(lds_sw(b, n, k1));
            }
#pragma unroll
            for (int mi = 0; mi < 4; ++mi)
#pragma unroll
                for (int ni = 0; ni < 4; ++ni)
                    mma_tf32(acc[mi][ni], af[mi], bf[ni]);
        }
        __syncthreads();
    }

#pragma unroll
    for (int mi = 0; mi < 4; ++mi) {
        int r1 = bm + wm * 64 + mi * 16 + (lane >> 2);
#pragma unroll
        for (int ni = 0; ni < 4; ++ni) {
            int cc = bn + wn * 32 + ni * 8 + (lane & 3) * 2;
            *(float2*)(C + (size_t)r1 * N + cc) =
                make_float2(acc[mi][ni][0], acc[mi][ni][1]);
            *(float2*)(C + (size_t)(r1 + 8) * N + cc) =
                make_float2(acc[mi][ni][2], acc[mi][ni][3]);
        }
    }
}

// ---------------------------------------------------------------------------
// RoPE + scatter, outputs tf32-rounded q/k/v in [B][H][T][D]
// ---------------------------------------------------------------------------
__global__ __launch_bounds__(256) void rope_scatter()
{
    int gid = blockIdx.x * 256 + threadIdx.x;
    int i = gid & 31;
    int h = (gid >> 5) % Hq;
    int bt = gid / (32 * Hq);
    int t = bt & (Tq - 1);
    int b = bt >> 10;

    const float* row = g_qkv + (size_t)bt * (3 * Cq);

    float ang = (float)t * exp2f(-(float)i * (13.2877123795494936f / 32.0f));
    float s, c;
    sincosf(ang, &s, &c);

    int base = h * 64;
    size_t dst = ((size_t)(b * Hq + h) * Tq + t) * 64;

    {
        float x1 = row[base + i];
        float x2 = row[base + i + 32];
        g_q[dst + i]      = __uint_as_float(cvt_tf32(x1 * c + x2 * s));
        g_q[dst + i + 32] = __uint_as_float(cvt_tf32(-x1 * s + x2 * c));
    }
    {
        float x1 = row[Cq + base + i];
        float x2 = row[Cq + base + i + 32];
        g_k[dst + i]      = __uint_as_float(cvt_tf32(x1 * c + x2 * s));
        g_k[dst + i + 32] = __uint_as_float(cvt_tf32(-x1 * s + x2 * c));
    }
    {
        g_v[dst + i]      = __uint_as_float(cvt_tf32(row[2 * Cq + base + i]));
        g_v[dst + i + 32] = __uint_as_float(cvt_tf32(row[2 * Cq + base + i + 32]));
    }
}

// ---------------------------------------------------------------------------
// Tensor-core flash attention (causal), tf32 mma.sync.
// Block = (qb128, h, b): 128 q rows, 256 threads (8 warps x 16 rows).
// kv tiles of 64 keys, double-buffered cp.async.
// smem floats: Ks[2][4096] swizzled | Vs[2][4608] stride 72 | Ps[8192] swizzled
// ---------------------------------------------------------------------------
#define ATTN2_SMEM_BYTES 102400

__device__ __forceinline__ void load_kv_tile(uint32_t ksm, uint32_t vsm,
                                             const float* kt, const float* vt,
                                             int tid)
{
    int s = tid >> 2, c0 = tid & 3;
#pragma unroll
    for (int i = 0; i < 4; ++i) {
        int c = c0 + i * 4;
        asm volatile("cp.async.cg.shared.global [%0], [%1], 16;"
                     :: "r"(ksm + s * 256 + ((c ^ (s & 7)) << 4)),
                        "l"(kt + s * 64 + c * 4) : "memory");
        asm volatile("cp.async.cg.shared.global [%0], [%1], 16;"
                     :: "r"(vsm + s * 288 + (c << 4)),
                        "l"(vt + s * 64 + c * 4) : "memory");
    }
    asm volatile("cp.async.commit_group;" ::: "memory");
}

__global__ __launch_bounds__(256) void attn_mma(const float* __restrict__ gq,
                                                const float* __restrict__ gk,
                                                const float* __restrict__ gv,
                                                float* __restrict__ gatt)
{
    extern __shared__ float sm2[];
    float* Ks = sm2;                // [2][4096]
    float* Vs = sm2 + 8192;         // [2][4608], stride 72
    float* Ps = sm2 + 17408;        // [8192] (Q staging, then per-warp P)

    const int tid = threadIdx.x;
    const int wid = tid >> 5;
    const int lane = tid & 31;
    const int g = lane >> 2;
    const int r = lane & 3;
    const int qb = (gridDim.x - 1) - blockIdx.x;   // heavy tiles first
    const int h = blockIdx.y;
    const int b = blockIdx.z;

    const float* qp = gq + ((size_t)(b * Hq + h) * Tq + qb * 128) * 64;
    const float* kp = gk + (size_t)(b * Hq + h) * Tq * 64;
    const float* vp = gv + (size_t)(b * Hq + h) * Tq * 64;
    const int nst = 2 * qb + 2;

    const uint32_t ksm = smem_u32(Ks);
    const uint32_t vsm = smem_u32(Vs);

    // prefetch kv tile 0
    load_kv_tile(ksm, vsm, kp, vp, tid);

    // stage Q (128x64) into Ps with swizzle, then lift fragments to registers
#pragma unroll
    for (int i = 0; i < 8; ++i) {
        int idx = tid + i * 256;
        int s = idx >> 4, c = idx & 15;
        float4 v = *(const float4*)(qp + s * 64 + c * 4);
        *(float4*)(Ps + s * 64 + ((c ^ (s & 7)) << 2)) = v;
    }
    __syncthreads();
    uint32_t qf[8][4];
    {
        int q0 = wid * 16 + g;
#pragma unroll
        for (int ks = 0; ks < 8; ++ks) {
            qf[ks][0] = __float_as_uint(Ps[swz(q0, ks * 8 + r)]);
            qf[ks][1] = __float_as_uint(Ps[swz(q0 + 8, ks * 8 + r)]);
            qf[ks][2] = __float_as_uint(Ps[swz(q0, ks * 8 + r + 4)]);
            qf[ks][3] = __float_as_uint(Ps[swz(q0 + 8, ks * 8 + r + 4)]);
        }
    }
    __syncthreads();

    float m0 = -1e30f, m1 = -1e30f, l0 = 0.0f, l1 = 0.0f;
    float o[8][4];
#pragma unroll
    for (int dt = 0; dt < 8; ++dt)
#pragma unroll
        for (int j = 0; j < 4; ++j) o[dt][j] = 0.0f;

    float* Pw = Ps + wid * 1024;
    const int qlo = qb * 128 + wid * 16;
    const int qr0 = qlo + g;

    for (int st = 0; st < nst; ++st) {
        if (st + 1 < nst) {
            load_kv_tile(ksm + ((st + 1) & 1) * 16384, vsm + ((st + 1) & 1) * 18432,
                         kp + (size_t)(st + 1) * 4096, vp + (size_t)(st + 1) * 4096, tid);
            asm volatile("cp.async.wait_group 1;" ::: "memory");
        } else {
            asm volatile("cp.async.wait_group 0;" ::: "memory");
        }
        __syncthreads();

        const int collo = st * 64;
        if (collo <= qlo + 15) {                 // warp not fully masked
            const float* kb = Ks + (st & 1) * 4096;
            const float* vb = Vs + (st & 1) * 4608;

            // S = Q K^T
            float s4[8][4];
#pragma unroll
            for (int nt = 0; nt < 8; ++nt)
#pragma unroll
                for (int j = 0; j < 4; ++j) s4[nt][j] = 0.0f;
#pragma unroll
            for (int ks = 0; ks < 8; ++ks)
#pragma unroll
                for (int nt = 0; nt < 8; ++nt) {
                    uint32_t bk[2];
                    bk[0] = __float_as_uint(kb[swz(nt * 8 + g, ks * 8 + r)]);
                    bk[1] = __float_as_uint(kb[swz(nt * 8 + g, ks * 8 + r + 4)]);
                    mma_tf32(s4[nt], qf[ks], bk);
                }

            const bool diag = (collo + 63 > qlo);
#pragma unroll
            for (int nt = 0; nt < 8; ++nt) {
                s4[nt][0] *= 0.125f; s4[nt][1] *= 0.125f;
                s4[nt][2] *= 0.125f; s4[nt][3] *= 0.125f;
                if (diag) {
                    int c0 = collo + nt * 8 + 2 * r;
                    if (c0     > qr0)     s4[nt][0] = -1e30f;
                    if (c0 + 1 > qr0)     s4[nt][1] = -1e30f;
                    if (c0     > qr0 + 8) s4[nt][2] = -1e30f;
                    if (c0 + 1 > qr0 + 8) s4[nt][3] = -1e30f;
                }
            }

            // online softmax (rows qr0 and qr0+8)
            float mx0 = -1e30f, mx1 = -1e30f;
#pragma unroll
            for (int nt = 0; nt < 8; ++nt) {
                mx0 = fmaxf(mx0, fmaxf(s4[nt][0], s4[nt][1]));
                mx1 = fmaxf(mx1, fmaxf(s4[nt][2], s4[nt][3]));
            }
            mx0 = fmaxf(mx0, __shfl_xor_sync(0xffffffffu, mx0, 1));
            mx0 = fmaxf(mx0, __shfl_xor_sync(0xffffffffu, mx0, 2));
            mx1 = fmaxf(mx1, __shfl_xor_sync(0xffffffffu, mx1, 1));
            mx1 = fmaxf(mx1, __shfl_xor_sync(0xffffffffu, mx1, 2));

            float mn0 = fmaxf(m0, mx0), mn1 = fmaxf(m1, mx1);
            float cr0 = __expf(m0 - mn0), cr1 = __expf(m1 - mn1);
            m0 = mn0; m1 = mn1;

            float sum0 = 0.0f, sum1 = 0.0f;
#pragma unroll
            for (int nt = 0; nt < 8; ++nt) {
                float p00 = __expf(s4[nt][0] - m0);
                float p01 = __expf(s4[nt][1] - m0);
                float p10 = __expf(s4[nt][2] - m1);
                float p11 = __expf(s4[nt][3] - m1);
                sum0 += p00 + p01;
                sum1 += p10 + p11;
                int d0 = nt * 8 + 2 * r;
                *(float2*)(Pw + swz(g, d0)) =
                    make_float2(__uint_as_float(cvt_tf32(p00)),
                                __uint_as_float(cvt_tf32(p01)));
                *(float2*)(Pw + swz(g + 8, d0)) =
                    make_float2(__uint_as_float(cvt_tf32(p10)),
                                __uint_as_float(cvt_tf32(p11)));
            }
            sum0 += __shfl_xor_sync(0xffffffffu, sum0, 1);
            sum0 += __shfl_xor_sync(0xffffffffu, sum0, 2);
            sum1 += __shfl_xor_sync(0xffffffffu, sum1, 1);
            sum1 += __shfl_xor_sync(0xffffffffu, sum1, 2);
            l0 = l0 * cr0 + sum0;
            l1 = l1 * cr1 + sum1;

#pragma unroll
            for (int dt = 0; dt < 8; ++dt) {
                o[dt][0] *= cr0; o[dt][1] *= cr0;
                o[dt][2] *= cr1; o[dt][3] *= cr1;
            }
            __syncwarp();

            // O += P V
#pragma unroll
            for (int ks = 0; ks < 8; ++ks) {
                uint32_t pa[4];
                pa[0] = __float_as_uint(Pw[swz(g, ks * 8 + r)]);
                pa[1] = __float_as_uint(Pw[swz(g + 8, ks * 8 + r)]);
                pa[2] = __float_as_uint(Pw[swz(g, ks * 8 + r + 4)]);
                pa[3] = __float_as_uint(Pw[swz(g + 8, ks * 8 + r + 4)]);
#pragma unroll
                for (int dt = 0; dt < 8; ++dt) {
                    uint32_t bv[2];
                    bv[0] = __float_as_uint(vb[(ks * 8 + r) * 72 + dt * 8 + g]);
                    bv[1] = __float_as_uint(vb[(ks * 8 + r + 4) * 72 + dt * 8 + g]);
                    mma_tf32(o[dt], pa, bv);
                }
            }
        }
        __syncthreads();   // protect K/V buffers & Ps before next iteration
    }

    // finalize: write tf32-rounded output (A operand of proj GEMM)
    float li0 = 1.0f / l0, li1 = 1.0f / l1;
    int t0 = qb * 128 + wid * 16 + g;
    float* ob = gatt + ((size_t)b * Tq + t0) * Cq + h * 64;
#pragma unroll
    for (int dt = 0; dt < 8; ++dt) {
        int cc = dt * 8 + 2 * r;
        *(float2*)(ob + cc) =
            make_float2(__uint_as_float(cvt_tf32(o[dt][0] * li0)),
                        __uint_as_float(cvt_tf32(o[dt][1] * li0)));
        *(float2*)(ob + 8 * Cq + cc) =
            make_float2(__uint_as_float(cvt_tf32(o[dt][2] * li1)),
                        __uint_as_float(cvt_tf32(o[dt][3] * li1)));
    }
}

// ---------------------------------------------------------------------------
// Launch
// ---------------------------------------------------------------------------
extern "C" void kernel_launch(void* const* d_in, const int* in_sizes, int n_in,
                              void* d_out, int out_size)
{
    const float* x      = (const float*)d_in[0];
    const float* w_qkv  = (const float*)d_in[1];
    const float* w_proj = (const float*)d_in[2];
    float* out = (float*)d_out;

    float *qkv, *q, *k, *v, *att, *xr, *wqr, *wpr;
    cudaGetSymbolAddress((void**)&qkv, g_qkv);
    cudaGetSymbolAddress((void**)&q, g_q);
    cudaGetSymbolAddress((void**)&k, g_k);
    cudaGetSymbolAddress((void**)&v, g_v);
    cudaGetSymbolAddress((void**)&att, g_att);
    cudaGetSymbolAddress((void**)&xr, g_xr);
    cudaGetSymbolAddress((void**)&wqr, g_wqkv_r);
    cudaGetSymbolAddress((void**)&wpr, g_wproj_r);

    const int M = Bq * Tq;  // 8192

    cudaFuncSetAttribute(gemm_tf32, cudaFuncAttributeMaxDynamicSharedMemorySize,
                         GEMM_SMEM_BYTES);
    cudaFuncSetAttribute(attn_mma, cudaFuncAttributeMaxDynamicSharedMemorySize,
                         ATTN2_SMEM_BYTES);

    // 0. tf32-round GEMM operands
    round_tf32_k<<<(M * Cq / 4 + 255) / 256, 256>>>(x, xr, M * Cq / 4);
    round_tf32_k<<<(3 * Cq * Cq / 4 + 255) / 256, 256>>>(w_qkv, wqr, 3 * Cq * Cq / 4);
    round_tf32_k<<<(Cq * Cq / 4 + 255) / 256, 256>>>(w_proj, wpr, Cq * Cq / 4);

    // 1. qkv = x @ w_qkv^T
    gemm_tf32<<<dim3((3 * Cq) / 128, M / 128), 256, GEMM_SMEM_BYTES>>>(
        xr, wqr, qkv, M, 3 * Cq, Cq);

    // 2. RoPE + scatter (tf32-rounded q/k/v)
    rope_scatter<<<(Bq * Tq * Hq * 32) / 256, 256>>>();

    // 3. Tensor-core causal flash attention
    attn_mma<<<dim3(Tq / 128, Hq, Bq), 256, ATTN2_SMEM_BYTES>>>(q, k, v, att);

    // 4. out = att @ w_proj^T
    gemm_tf32<<<dim3(Cq / 128, M / 128), 256, GEMM_SMEM_BYTES>>>(
        att, wpr, out, M, Cq, Cq);
}

// round 12
// speedup vs baseline: 3.1714x; 1.0637x over previous
#include <cuda_runtime.h>
#include <math.h>
#include <cstdint>

// Problem dims
#define Bq 8
#define Tq 1024
#define Cq 768
#define Hq 12
#define Dq 64

// Scratch (device globals: allocation-free rule)
__device__ float g_qkv[(size_t)Bq * Tq * 3 * Cq];   // [B*T][2304]
__device__ float g_q[(size_t)Bq * Hq * Tq * Dq];    // [B][H][T][D] (tf32-rounded)
__device__ float g_k[(size_t)Bq * Hq * Tq * Dq];
__device__ float g_v[(size_t)Bq * Hq * Tq * Dq];
__device__ float g_att[(size_t)Bq * Tq * Cq];       // [B][T][C]   (tf32-rounded)
__device__ float g_xr[(size_t)Bq * Tq * Cq];        // rounded x
__device__ float g_wqkv_r[(size_t)3 * Cq * Cq];     // rounded w_qkv
__device__ float g_wproj_r[(size_t)Cq * Cq];        // rounded w_proj

// ---------------------------------------------------------------------------
// Helpers
// ---------------------------------------------------------------------------
__device__ __forceinline__ uint32_t smem_u32(const void* p) {
    uint32_t a;
    asm("{ .reg .u64 t; cvta.to.shared.u64 t, %1; cvt.u32.u64 %0, t; }"
        : "=r"(a) : "l"(p));
    return a;
}

__device__ __forceinline__ uint32_t cvt_tf32(float v) {
    uint32_t u;
    asm("cvt.rna.tf32.f32 %0, %1;" : "=r"(u) : "f"(v));
    return u;
}

__device__ __forceinline__ void mma_tf32(float* d, const uint32_t* a,
                                         const uint32_t* b) {
    asm volatile(
        "mma.sync.aligned.m16n8k8.row.col.f32.tf32.tf32.f32 "
        "{%0,%1,%2,%3}, {%4,%5,%6,%7}, {%8,%9}, {%0,%1,%2,%3};"
        : "+f"(d[0]), "+f"(d[1]), "+f"(d[2]), "+f"(d[3])
        : "r"(a[0]), "r"(a[1]), "r"(a[2]), "r"(a[3]), "r"(b[0]), "r"(b[1]));
}

// XOR-swizzled float index: row-major [s][64], 16B chunks XORed by (s&7)
__device__ __forceinline__ int swz(int s, int d) {
    return s * 64 + ((((d >> 2) ^ (s & 7)) << 2) | (d & 3));
}

// ---------------------------------------------------------------------------
// Round-to-tf32 copy kernel (n divisible by 4)
// ---------------------------------------------------------------------------
__global__ __launch_bounds__(256) void round_tf32_k(const float* __restrict__ in,
                                                    float* __restrict__ out, int n4)
{
    int i = blockIdx.x * 256 + threadIdx.x;
    if (i < n4) {
        float4 v = ((const float4*)in)[i];
        v.x = __uint_as_float(cvt_tf32(v.x));
        v.y = __uint_as_float(cvt_tf32(v.y));
        v.z = __uint_as_float(cvt_tf32(v.z));
        v.w = __uint_as_float(cvt_tf32(v.w));
        ((float4*)out)[i] = v;
    }
}

// ---------------------------------------------------------------------------
// tf32 mma.sync GEMM: C[m][n] = sum_k A[m*K+k] * W[n*K+k]
// Inputs must already be tf32-rounded. BM=128, BN=128, BK=32, 256 threads.
// Swizzle addressing precomputed: addr(ks) = addr0 ^ (ks*8) (bit-disjoint).
// ---------------------------------------------------------------------------
#define GEMM_SMEM_BYTES (4 * 16384)

__global__ __launch_bounds__(256, 2)
void gemm_tf32(const float* __restrict__ A, const float* __restrict__ W,
               float* __restrict__ C, int M, int N, int K)
{
    extern __shared__ float sm[];
    const uint32_t sb = smem_u32(sm);

    const int tid = threadIdx.x;
    const int wid = tid >> 5;
    const int lane = tid & 31;
    const int g = lane >> 2;
    const int r = lane & 3;
    const int wm = wid & 1;
    const int wn = wid >> 1;
    const int bm = blockIdx.y * 128;
    const int bn = blockIdx.x * 128;
    const int nK = K >> 5;

    const int c4 = tid & 7;
    const int r0 = tid >> 3;
    const float* Ag = A + (size_t)(bm + r0) * K + c4 * 4;
    const float* Wg = W + (size_t)(bn + r0) * K + c4 * 4;

    // Precomputed fragment base indices (tile rows of 32 floats):
    // idx0 = row*32 + ((row&7)<<2) + r ; access = idx0 ^ (ks*8) / ^(ks*8+4)
    uint32_t ia0[4][2], ib0[4];
#pragma unroll
    for (int mi = 0; mi < 4; ++mi) {
        int r1 = wm * 64 + mi * 16 + g;
        uint32_t lo = ((r1 & 7) << 2) + r;
        ia0[mi][0] = r1 * 32 + lo;
        ia0[mi][1] = (r1 + 8) * 32 + lo;
    }
#pragma unroll
    for (int ni = 0; ni < 4; ++ni) {
        int n = wn * 32 + ni * 8 + g;
        ib0[ni] = n * 32 + ((n & 7) << 2) + r;
    }

    float acc[4][4][4];
#pragma unroll
    for (int mi = 0; mi < 4; ++mi)
#pragma unroll
        for (int ni = 0; ni < 4; ++ni)
#pragma unroll
            for (int j = 0; j < 4; ++j) acc[mi][ni][j] = 0.0f;

    {
        uint32_t sa = sb;
        uint32_t sw = sb + 32768;
#pragma unroll
        for (int i = 0; i < 4; ++i) {
            int row = r0 + i * 32;
            uint32_t off = row * 128 + ((c4 ^ (row & 7)) << 4);
            asm volatile("cp.async.cg.shared.global [%0], [%1], 16;"
                         :: "r"(sa + off), "l"(Ag + (size_t)i * 32 * K) : "memory");
            asm volatile("cp.async.cg.shared.global [%0], [%1], 16;"
                         :: "r"(sw + off), "l"(Wg + (size_t)i * 32 * K) : "memory");
        }
        asm volatile("cp.async.commit_group;" ::: "memory");
    }

    for (int kt = 0; kt < nK; ++kt) {
        if (kt + 1 < nK) {
            int nb = (kt + 1) & 1;
            uint32_t sa = sb + nb * 16384;
            uint32_t sw = sb + 32768 + nb * 16384;
            const float* ag = Ag + (size_t)(kt + 1) * 32;
            const float* wg = Wg + (size_t)(kt + 1) * 32;
#pragma unroll
            for (int i = 0; i < 4; ++i) {
                int row = r0 + i * 32;
                uint32_t off = row * 128 + ((c4 ^ (row & 7)) << 4);
                asm volatile("cp.async.cg.shared.global [%0], [%1], 16;"
                             :: "r"(sa + off), "l"(ag + (size_t)i * 32 * K) : "memory");
                asm volatile("cp.async.cg.shared.global [%0], [%1], 16;"
                             :: "r"(sw + off), "l"(wg + (size_t)i * 32 * K) : "memory");
            }
            asm volatile("cp.async.commit_group;" ::: "memory");
            asm volatile("cp.async.wait_group 1;" ::: "memory");
        } else {
            asm volatile("cp.async.wait_group 0;" ::: "memory");
        }
        __syncthreads();

        const int buf = kt & 1;
        const float* a = sm + buf * 4096;
        const float* b = sm + 8192 + buf * 4096;

#pragma unroll
        for (int ks = 0; ks < 4; ++ks) {
            const uint32_t x0 = ks * 8, x1 = ks * 8 + 4;

            uint32_t af[4][4];
#pragma unroll
            for (int mi = 0; mi < 4; ++mi) {
                af[mi][0] = __float_as_uint(a[ia0[mi][0] ^ x0]);
                af[mi][1] = __float_as_uint(a[ia0[mi][1] ^ x0]);
                af[mi][2] = __float_as_uint(a[ia0[mi][0] ^ x1]);
                af[mi][3] = __float_as_uint(a[ia0[mi][1] ^ x1]);
            }
            uint32_t bf[4][2];
#pragma unroll
            for (int ni = 0; ni < 4; ++ni) {
                bf[ni][0] = __float_as_uint(b[ib0[ni] ^ x0]);
                bf[ni][1] = __float_as_uint(b[ib0[ni] ^ x1]);
            }
#pragma unroll
            for (int mi = 0; mi < 4; ++mi)
#pragma unroll
                for (int ni = 0; ni < 4; ++ni)
                    mma_tf32(acc[mi][ni], af[mi], bf[ni]);
        }
        __syncthreads();
    }

#pragma unroll
    for (int mi = 0; mi < 4; ++mi) {
        int r1 = bm + wm * 64 + mi * 16 + g;
#pragma unroll
        for (int ni = 0; ni < 4; ++ni) {
            int cc = bn + wn * 32 + ni * 8 + r * 2;
            *(float2*)(C + (size_t)r1 * N + cc) =
                make_float2(acc[mi][ni][0], acc[mi][ni][1]);
            *(float2*)(C + (size_t)(r1 + 8) * N + cc) =
                make_float2(acc[mi][ni][2], acc[mi][ni][3]);
        }
    }
}

// ---------------------------------------------------------------------------
// RoPE + scatter, outputs tf32-rounded q/k/v in [B][H][T][D]
// ---------------------------------------------------------------------------
__global__ __launch_bounds__(256) void rope_scatter()
{
    int gid = blockIdx.x * 256 + threadIdx.x;
    int i = gid & 31;
    int h = (gid >> 5) % Hq;
    int bt = gid / (32 * Hq);
    int t = bt & (Tq - 1);
    int b = bt >> 10;

    const float* row = g_qkv + (size_t)bt * (3 * Cq);

    float ang = (float)t * exp2f(-(float)i * (13.2877123795494936f / 32.0f));
    float s, c;
    sincosf(ang, &s, &c);

    int base = h * 64;
    size_t dst = ((size_t)(b * Hq + h) * Tq + t) * 64;

    {
        float x1 = row[base + i];
        float x2 = row[base + i + 32];
        g_q[dst + i]      = __uint_as_float(cvt_tf32(x1 * c + x2 * s));
        g_q[dst + i + 32] = __uint_as_float(cvt_tf32(-x1 * s + x2 * c));
    }
    {
        float x1 = row[Cq + base + i];
        float x2 = row[Cq + base + i + 32];
        g_k[dst + i]      = __uint_as_float(cvt_tf32(x1 * c + x2 * s));
        g_k[dst + i + 32] = __uint_as_float(cvt_tf32(-x1 * s + x2 * c));
    }
    {
        g_v[dst + i]      = __uint_as_float(cvt_tf32(row[2 * Cq + base + i]));
        g_v[dst + i + 32] = __uint_as_float(cvt_tf32(row[2 * Cq + base + i + 32]));
    }
}

// ---------------------------------------------------------------------------
// Tensor-core flash attention (causal), tf32 mma.sync.
// Block = (qb128, h, b): 128 q rows, 256 threads (8 warps x 16 rows).
// kv tiles of 64 keys, double-buffered cp.async.
// smem floats: Ks[2][4096] swizzled | Vs[2][4608] stride 72 | Ps[8192] swizzled
// ---------------------------------------------------------------------------
#define ATTN2_SMEM_BYTES 102400

__device__ __forceinline__ void load_kv_tile(uint32_t ksm, uint32_t vsm,
                                             const float* kt, const float* vt,
                                             int tid)
{
    int s = tid >> 2, c0 = tid & 3;
#pragma unroll
    for (int i = 0; i < 4; ++i) {
        int c = c0 + i * 4;
        asm volatile("cp.async.cg.shared.global [%0], [%1], 16;"
                     :: "r"(ksm + s * 256 + ((c ^ (s & 7)) << 4)),
                        "l"(kt + s * 64 + c * 4) : "memory");
        asm volatile("cp.async.cg.shared.global [%0], [%1], 16;"
                     :: "r"(vsm + s * 288 + (c << 4)),
                        "l"(vt + s * 64 + c * 4) : "memory");
    }
    asm volatile("cp.async.commit_group;" ::: "memory");
}

__global__ __launch_bounds__(256) void attn_mma(const float* __restrict__ gq,
                                                const float* __restrict__ gk,
                                                const float* __restrict__ gv,
                                                float* __restrict__ gatt)
{
    extern __shared__ float sm2[];
    float* Ks = sm2;                // [2][4096]
    float* Vs = sm2 + 8192;         // [2][4608], stride 72
    float* Ps = sm2 + 17408;        // [8192] (Q staging, then per-warp P)

    const int tid = threadIdx.x;
    const int wid = tid >> 5;
    const int lane = tid & 31;
    const int g = lane >> 2;
    const int r = lane & 3;
    const int qb = (gridDim.x - 1) - blockIdx.x;   // heavy tiles first
    const int h = blockIdx.y;
    const int b = blockIdx.z;

    const float* qp = gq + ((size_t)(b * Hq + h) * Tq + qb * 128) * 64;
    const float* kp = gk + (size_t)(b * Hq + h) * Tq * 64;
    const float* vp = gv + (size_t)(b * Hq + h) * Tq * 64;
    const int nst = 2 * qb + 2;

    const uint32_t ksm = smem_u32(Ks);
    const uint32_t vsm = smem_u32(Vs);

    // prefetch kv tile 0
    load_kv_tile(ksm, vsm, kp, vp, tid);

    // stage Q (128x64) into Ps with swizzle, then lift fragments to registers
#pragma unroll
    for (int i = 0; i < 8; ++i) {
        int idx = tid + i * 256;
        int s = idx >> 4, c = idx & 15;
        float4 v = *(const float4*)(qp + s * 64 + c * 4);
        *(float4*)(Ps + s * 64 + ((c ^ (s & 7)) << 2)) = v;
    }
    __syncthreads();
    uint32_t qf[8][4];
    {
        int q0 = wid * 16 + g;
#pragma unroll
        for (int ks = 0; ks < 8; ++ks) {
            qf[ks][0] = __float_as_uint(Ps[swz(q0, ks * 8 + r)]);
            qf[ks][1] = __float_as_uint(Ps[swz(q0 + 8, ks * 8 + r)]);
            qf[ks][2] = __float_as_uint(Ps[swz(q0, ks * 8 + r + 4)]);
            qf[ks][3] = __float_as_uint(Ps[swz(q0 + 8, ks * 8 + r + 4)]);
        }
    }
    __syncthreads();

    // Precomputed swizzle bases (rows of 64 floats):
    // K rows nt*8+g:  ikb[nt] ^ (ks*8) / ^(ks*8+4)
    uint32_t ikb[8];
#pragma unroll
    for (int nt = 0; nt < 8; ++nt) {
        int row = nt * 8 + g;
        ikb[nt] = row * 64 + ((row & 7) << 2) + r;
    }
    // P fragment loads, rows g and g+8: ipa ^ (ks*8) / ^(ks*8+4)
    const uint32_t ipa0 = g * 64 + ((g & 7) << 2) + r;
    const uint32_t ipa1 = (g + 8) * 64 + ((g & 7) << 2) + r;
    // P stores (float2 at d0 = nt*8 + 2r): idx = ipw ^ (nt*8)
    const uint32_t pw_lo = (((r >> 1) ^ (g & 7)) << 2) + ((2 * r) & 3);
    const uint32_t ipw0 = g * 64 + pw_lo;
    const uint32_t ipw1 = (g + 8) * 64 + pw_lo;

    float m0 = -1e30f, m1 = -1e30f, l0 = 0.0f, l1 = 0.0f;
    float o[8][4];
#pragma unroll
    for (int dt = 0; dt < 8; ++dt)
#pragma unroll
        for (int j = 0; j < 4; ++j) o[dt][j] = 0.0f;

    float* Pw = Ps + wid * 1024;
    const int qlo = qb * 128 + wid * 16;
    const int qr0 = qlo + g;

    for (int st = 0; st < nst; ++st) {
        if (st + 1 < nst) {
            load_kv_tile(ksm + ((st + 1) & 1) * 16384, vsm + ((st + 1) & 1) * 18432,
                         kp + (size_t)(st + 1) * 4096, vp + (size_t)(st + 1) * 4096, tid);
            asm volatile("cp.async.wait_group 1;" ::: "memory");
        } else {
            asm volatile("cp.async.wait_group 0;" ::: "memory");
        }
        __syncthreads();

        const int collo = st * 64;
        if (collo <= qlo + 15) {                 // warp not fully masked
            const float* kb = Ks + (st & 1) * 4096;
            const float* vb = Vs + (st & 1) * 4608;

            // S = Q K^T
            float s4[8][4];
#pragma unroll
            for (int nt = 0; nt < 8; ++nt)
#pragma unroll
                for (int j = 0; j < 4; ++j) s4[nt][j] = 0.0f;
#pragma unroll
            for (int ks = 0; ks < 8; ++ks) {
                const uint32_t x0 = ks * 8, x1 = ks * 8 + 4;
#pragma unroll
                for (int nt = 0; nt < 8; ++nt) {
                    uint32_t bk[2];
                    bk[0] = __float_as_uint(kb[ikb[nt] ^ x0]);
                    bk[1] = __float_as_uint(kb[ikb[nt] ^ x1]);
                    mma_tf32(s4[nt], qf[ks], bk);
                }
            }

            const bool diag = (collo + 63 > qlo);
#pragma unroll
            for (int nt = 0; nt < 8; ++nt) {
                s4[nt][0] *= 0.125f; s4[nt][1] *= 0.125f;
                s4[nt][2] *= 0.125f; s4[nt][3] *= 0.125f;
                if (diag) {
                    int c0 = collo + nt * 8 + 2 * r;
                    if (c0     > qr0)     s4[nt][0] = -1e30f;
                    if (c0 + 1 > qr0)     s4[nt][1] = -1e30f;
                    if (c0     > qr0 + 8) s4[nt][2] = -1e30f;
                    if (c0 + 1 > qr0 + 8) s4[nt][3] = -1e30f;
                }
            }

            // online softmax (rows qr0 and qr0+8)
            float mx0 = -1e30f, mx1 = -1e30f;
#pragma unroll
            for (int nt = 0; nt < 8; ++nt) {
                mx0 = fmaxf(mx0, fmaxf(s4[nt][0], s4[nt][1]));
                mx1 = fmaxf(mx1, fmaxf(s4[nt][2], s4[nt][3]));
            }
            mx0 = fmaxf(mx0, __shfl_xor_sync(0xffffffffu, mx0, 1));
            mx0 = fmaxf(mx0, __shfl_xor_sync(0xffffffffu, mx0, 2));
            mx1 = fmaxf(mx1, __shfl_xor_sync(0xffffffffu, mx1, 1));
            mx1 = fmaxf(mx1, __shfl_xor_sync(0xffffffffu, mx1, 2));

            float mn0 = fmaxf(m0, mx0), mn1 = fmaxf(m1, mx1);
            float cr0 = __expf(m0 - mn0), cr1 = __expf(m1 - mn1);
            m0 = mn0; m1 = mn1;

            float sum0 = 0.0f, sum1 = 0.0f;
#pragma unroll
            for (int nt = 0; nt < 8; ++nt) {
                float p00 = __expf(s4[nt][0] - m0);
                float p01 = __expf(s4[nt][1] - m0);
                float p10 = __expf(s4[nt][2] - m1);
                float p11 = __expf(s4[nt][3] - m1);
                sum0 += p00 + p01;
                sum1 += p10 + p11;
                *(float2*)(Pw + (ipw0 ^ (uint32_t)(nt * 8))) =
                    make_float2(__uint_as_float(cvt_tf32(p00)),
                                __uint_as_float(cvt_tf32(p01)));
                *(float2*)(Pw + (ipw1 ^ (uint32_t)(nt * 8))) =
                    make_float2(__uint_as_float(cvt_tf32(p10)),
                                __uint_as_float(cvt_tf32(p11)));
            }
            sum0 += __shfl_xor_sync(0xffffffffu, sum0, 1);
            sum0 += __shfl_xor_sync(0xffffffffu, sum0, 2);
            sum1 += __shfl_xor_sync(0xffffffffu, sum1, 1);
            sum1 += __shfl_xor_sync(0xffffffffu, sum1, 2);
            l0 = l0 * cr0 + sum0;
            l1 = l1 * cr1 + sum1;

#pragma unroll
            for (int dt = 0; dt < 8; ++dt) {
                o[dt][0] *= cr0; o[dt][1] *= cr0;
                o[dt][2] *= cr1; o[dt][3] *= cr1;
            }
            __syncwarp();

            // O += P V
#pragma unroll
            for (int ks = 0; ks < 8; ++ks) {
                const uint32_t x0 = ks * 8, x1 = ks * 8 + 4;
                uint32_t pa[4];
                pa[0] = __float_as_uint(Pw[ipa0 ^ x0]);
                pa[1] = __float_as_uint(Pw[ipa1 ^ x0]);
                pa[2] = __float_as_uint(Pw[ipa0 ^ x1]);
                pa[3] = __float_as_uint(Pw[ipa1 ^ x1]);
#pragma unroll
                for (int dt = 0; dt < 8; ++dt) {
                    uint32_t bv[2];
                    bv[0] = __float_as_uint(vb[(ks * 8 + r) * 72 + dt * 8 + g]);
                    bv[1] = __float_as_uint(vb[(ks * 8 + r + 4) * 72 + dt * 8 + g]);
                    mma_tf32(o[dt], pa, bv);
                }
            }
        }
        __syncthreads();   // protect K/V buffers & Ps before next iteration
    }

    // finalize: write tf32-rounded output (A operand of proj GEMM)
    float li0 = 1.0f / l0, li1 = 1.0f / l1;
    int t0 = qb * 128 + wid * 16 + g;
    float* ob = gatt + ((size_t)b * Tq + t0) * Cq + h * 64;
#pragma unroll
    for (int dt = 0; dt < 8; ++dt) {
        int cc = dt * 8 + 2 * r;
        *(float2*)(ob + cc) =
            make_float2(__uint_as_float(cvt_tf32(o[dt][0] * li0)),
                        __uint_as_float(cvt_tf32(o[dt][1] * li0)));
        *(float2*)(ob + 8 * Cq + cc) =
            make_float2(__uint_as_float(cvt_tf32(o[dt][2] * li1)),
                        __uint_as_float(cvt_tf32(o[dt][3] * li1)));
    }
}

// ---------------------------------------------------------------------------
// Launch
// ---------------------------------------------------------------------------
extern "C" void kernel_launch(void* const* d_in, const int* in_sizes, int n_in,
                              void* d_out, int out_size)
{
    const float* x      = (const float*)d_in[0];
    const float* w_qkv  = (const float*)d_in[1];
    const float* w_proj = (const float*)d_in[2];
    float* out = (float*)d_out;

    float *qkv, *q, *k, *v, *att, *xr, *wqr, *wpr;
    cudaGetSymbolAddress((void**)&qkv, g_qkv);
    cudaGetSymbolAddress((void**)&q, g_q);
    cudaGetSymbolAddress((void**)&k, g_k);
    cudaGetSymbolAddress((void**)&v, g_v);
    cudaGetSymbolAddress((void**)&att, g_att);
    cudaGetSymbolAddress((void**)&xr, g_xr);
    cudaGetSymbolAddress((void**)&wqr, g_wqkv_r);
    cudaGetSymbolAddress((void**)&wpr, g_wproj_r);

    const int M = Bq * Tq;  // 8192

    cudaFuncSetAttribute(gemm_tf32, cudaFuncAttributeMaxDynamicSharedMemorySize,
                         GEMM_SMEM_BYTES);
    cudaFuncSetAttribute(attn_mma, cudaFuncAttributeMaxDynamicSharedMemorySize,
                         ATTN2_SMEM_BYTES);

    // 0. tf32-round GEMM operands
    round_tf32_k<<<(M * Cq / 4 + 255) / 256, 256>>>(x, xr, M * Cq / 4);
    round_tf32_k<<<(3 * Cq * Cq / 4 + 255) / 256, 256>>>(w_qkv, wqr, 3 * Cq * Cq / 4);
    round_tf32_k<<<(Cq * Cq / 4 + 255) / 256, 256>>>(w_proj, wpr, Cq * Cq / 4);

    // 1. qkv = x @ w_qkv^T
    gemm_tf32<<<dim3((3 * Cq) / 128, M / 128), 256, GEMM_SMEM_BYTES>>>(
        xr, wqr, qkv, M, 3 * Cq, Cq);

    // 2. RoPE + scatter (tf32-rounded q/k/v)
    rope_scatter<<<(Bq * Tq * Hq * 32) / 256, 256>>>();

    // 3. Tensor-core causal flash attention
    attn_mma<<<dim3(Tq / 128, Hq, Bq), 256, ATTN2_SMEM_BYTES>>>(q, k, v, att);

    // 4. out = att @ w_proj^T
    gemm_tf32<<<dim3(Cq / 128, M / 128), 256, GEMM_SMEM_BYTES>>>(
        att, wpr, out, M, Cq, Cq);
}

// round 13
// speedup vs baseline: 3.3146x; 1.0451x over previous
#include <cuda_runtime.h>
#include <math.h>
#include <cstdint>

// Problem dims
#define Bq 8
#define Tq 1024
#define Cq 768
#define Hq 12
#define Dq 64

// Scratch (device globals: allocation-free rule)
__device__ float g_qkv[(size_t)Bq * Tq * 3 * Cq];   // [B*T][2304]
__device__ float g_q[(size_t)Bq * Hq * Tq * Dq];    // [B][H][T][D] (tf32-rounded)
__device__ float g_k[(size_t)Bq * Hq * Tq * Dq];
__device__ float g_v[(size_t)Bq * Hq * Tq * Dq];
__device__ float g_att[(size_t)Bq * Tq * Cq];       // [B][T][C]   (tf32-rounded)
__device__ float g_xr[(size_t)Bq * Tq * Cq];        // rounded x
__device__ float g_wqkv_r[(size_t)3 * Cq * Cq];     // rounded w_qkv
__device__ float g_wproj_r[(size_t)Cq * Cq];        // rounded w_proj

// ---------------------------------------------------------------------------
// Helpers
// ---------------------------------------------------------------------------
__device__ __forceinline__ uint32_t smem_u32(const void* p) {
    uint32_t a;
    asm("{ .reg .u64 t; cvta.to.shared.u64 t, %1; cvt.u32.u64 %0, t; }"
        : "=r"(a) : "l"(p));
    return a;
}

__device__ __forceinline__ uint32_t cvt_tf32(float v) {
    uint32_t u;
    asm("cvt.rna.tf32.f32 %0, %1;" : "=r"(u) : "f"(v));
    return u;
}

__device__ __forceinline__ void mma_tf32(float* d, const uint32_t* a,
                                         const uint32_t* b) {
    asm volatile(
        "mma.sync.aligned.m16n8k8.row.col.f32.tf32.tf32.f32 "
        "{%0,%1,%2,%3}, {%4,%5,%6,%7}, {%8,%9}, {%0,%1,%2,%3};"
        : "+f"(d[0]), "+f"(d[1]), "+f"(d[2]), "+f"(d[3])
        : "r"(a[0]), "r"(a[1]), "r"(a[2]), "r"(a[3]), "r"(b[0]), "r"(b[1]));
}

// XOR-swizzled float index: row-major [s][64], 16B chunks XORed by (s&7)
__device__ __forceinline__ int swz(int s, int d) {
    return s * 64 + ((((d >> 2) ^ (s & 7)) << 2) | (d & 3));
}

// ---------------------------------------------------------------------------
// Round-to-tf32 copy kernel (n divisible by 4)
// ---------------------------------------------------------------------------
__global__ __launch_bounds__(256) void round_tf32_k(const float* __restrict__ in,
                                                    float* __restrict__ out, int n4)
{
    int i = blockIdx.x * 256 + threadIdx.x;
    if (i < n4) {
        float4 v = ((const float4*)in)[i];
        v.x = __uint_as_float(cvt_tf32(v.x));
        v.y = __uint_as_float(cvt_tf32(v.y));
        v.z = __uint_as_float(cvt_tf32(v.z));
        v.w = __uint_as_float(cvt_tf32(v.w));
        ((float4*)out)[i] = v;
    }
}

// ---------------------------------------------------------------------------
// tf32 mma.sync GEMM: C[m][n] = sum_k A[m*K+k] * W[n*K+k]
// Inputs must already be tf32-rounded.
// BM=128, BN=128, BK=32, 128 threads (4 warps, 2x2, warp tile 64x64).
// Swizzle addressing precomputed: addr(ks) = addr0 ^ (ks*8) (bit-disjoint).
// ---------------------------------------------------------------------------
#define GEMM_SMEM_BYTES (4 * 16384)

__global__ __launch_bounds__(128, 2)
void gemm_tf32(const float* __restrict__ A, const float* __restrict__ W,
               float* __restrict__ C, int M, int N, int K)
{
    extern __shared__ float sm[];
    const uint32_t sb = smem_u32(sm);

    const int tid = threadIdx.x;
    const int wid = tid >> 5;
    const int lane = tid & 31;
    const int g = lane >> 2;
    const int r = lane & 3;
    const int wm = wid & 1;
    const int wn = wid >> 1;
    const int bm = blockIdx.y * 128;
    const int bn = blockIdx.x * 128;
    const int nK = K >> 5;

    const int c4 = tid & 7;
    const int r0 = tid >> 3;          // 0..15
    const float* Ag = A + (size_t)(bm + r0) * K + c4 * 4;
    const float* Wg = W + (size_t)(bn + r0) * K + c4 * 4;

    // Fragment base indices (tile rows of 32 floats):
    // idx0 = row*32 + ((row&7)<<2) + r ; access = idx0 ^ (ks*8) / ^(ks*8+4)
    uint32_t ia0[4][2], ib0[8];
#pragma unroll
    for (int mi = 0; mi < 4; ++mi) {
        int r1 = wm * 64 + mi * 16 + g;
        uint32_t lo = ((r1 & 7) << 2) + r;
        ia0[mi][0] = r1 * 32 + lo;
        ia0[mi][1] = (r1 + 8) * 32 + lo;
    }
#pragma unroll
    for (int ni = 0; ni < 8; ++ni) {
        int n = wn * 64 + ni * 8 + g;
        ib0[ni] = n * 32 + ((n & 7) << 2) + r;
    }

    float acc[4][8][4];
#pragma unroll
    for (int mi = 0; mi < 4; ++mi)
#pragma unroll
        for (int ni = 0; ni < 8; ++ni)
#pragma unroll
            for (int j = 0; j < 4; ++j) acc[mi][ni][j] = 0.0f;

    {
        uint32_t sa = sb;
        uint32_t sw = sb + 32768;
#pragma unroll
        for (int i = 0; i < 8; ++i) {
            int row = r0 + i * 16;
            uint32_t off = row * 128 + ((c4 ^ (row & 7)) << 4);
            asm volatile("cp.async.cg.shared.global [%0], [%1], 16;"
                         :: "r"(sa + off), "l"(Ag + (size_t)i * 16 * K) : "memory");
            asm volatile("cp.async.cg.shared.global [%0], [%1], 16;"
                         :: "r"(sw + off), "l"(Wg + (size_t)i * 16 * K) : "memory");
        }
        asm volatile("cp.async.commit_group;" ::: "memory");
    }

    for (int kt = 0; kt < nK; ++kt) {
        if (kt + 1 < nK) {
            int nb = (kt + 1) & 1;
            uint32_t sa = sb + nb * 16384;
            uint32_t sw = sb + 32768 + nb * 16384;
            const float* ag = Ag + (size_t)(kt + 1) * 32;
            const float* wg = Wg + (size_t)(kt + 1) * 32;
#pragma unroll
            for (int i = 0; i < 8; ++i) {
                int row = r0 + i * 16;
                uint32_t off = row * 128 + ((c4 ^ (row & 7)) << 4);
                asm volatile("cp.async.cg.shared.global [%0], [%1], 16;"
                             :: "r"(sa + off), "l"(ag + (size_t)i * 16 * K) : "memory");
                asm volatile("cp.async.cg.shared.global [%0], [%1], 16;"
                             :: "r"(sw + off), "l"(wg + (size_t)i * 16 * K) : "memory");
            }
            asm volatile("cp.async.commit_group;" ::: "memory");
            asm volatile("cp.async.wait_group 1;" ::: "memory");
        } else {
            asm volatile("cp.async.wait_group 0;" ::: "memory");
        }
        __syncthreads();

        const int buf = kt & 1;
        const float* a = sm + buf * 4096;
        const float* b = sm + 8192 + buf * 4096;

#pragma unroll
        for (int ks = 0; ks < 4; ++ks) {
            const uint32_t x0 = ks * 8, x1 = ks * 8 + 4;

            uint32_t af[4][4];
#pragma unroll
            for (int mi = 0; mi < 4; ++mi) {
                af[mi][0] = __float_as_uint(a[ia0[mi][0] ^ x0]);
                af[mi][1] = __float_as_uint(a[ia0[mi][1] ^ x0]);
                af[mi][2] = __float_as_uint(a[ia0[mi][0] ^ x1]);
                af[mi][3] = __float_as_uint(a[ia0[mi][1] ^ x1]);
            }
            uint32_t bf[8][2];
#pragma unroll
            for (int ni = 0; ni < 8; ++ni) {
                bf[ni][0] = __float_as_uint(b[ib0[ni] ^ x0]);
                bf[ni][1] = __float_as_uint(b[ib0[ni] ^ x1]);
            }
#pragma unroll
            for (int mi = 0; mi < 4; ++mi)
#pragma unroll
                for (int ni = 0; ni < 8; ++ni)
                    mma_tf32(acc[mi][ni], af[mi], bf[ni]);
        }
        __syncthreads();
    }

#pragma unroll
    for (int mi = 0; mi < 4; ++mi) {
        int r1 = bm + wm * 64 + mi * 16 + g;
#pragma unroll
        for (int ni = 0; ni < 8; ++ni) {
            int cc = bn + wn * 64 + ni * 8 + r * 2;
            *(float2*)(C + (size_t)r1 * N + cc) =
                make_float2(acc[mi][ni][0], acc[mi][ni][1]);
            *(float2*)(C + (size_t)(r1 + 8) * N + cc) =
                make_float2(acc[mi][ni][2], acc[mi][ni][3]);
        }
    }
}

// ---------------------------------------------------------------------------
// RoPE + scatter, outputs tf32-rounded q/k/v in [B][H][T][D]
// ---------------------------------------------------------------------------
__global__ __launch_bounds__(256) void rope_scatter()
{
    int gid = blockIdx.x * 256 + threadIdx.x;
    int i = gid & 31;
    int h = (gid >> 5) % Hq;
    int bt = gid / (32 * Hq);
    int t = bt & (Tq - 1);
    int b = bt >> 10;

    const float* row = g_qkv + (size_t)bt * (3 * Cq);

    float ang = (float)t * exp2f(-(float)i * (13.2877123795494936f / 32.0f));
    float s, c;
    sincosf(ang, &s, &c);

    int base = h * 64;
    size_t dst = ((size_t)(b * Hq + h) * Tq + t) * 64;

    {
        float x1 = row[base + i];
        float x2 = row[base + i + 32];
        g_q[dst + i]      = __uint_as_float(cvt_tf32(x1 * c + x2 * s));
        g_q[dst + i + 32] = __uint_as_float(cvt_tf32(-x1 * s + x2 * c));
    }
    {
        float x1 = row[Cq + base + i];
        float x2 = row[Cq + base + i + 32];
        g_k[dst + i]      = __uint_as_float(cvt_tf32(x1 * c + x2 * s));
        g_k[dst + i + 32] = __uint_as_float(cvt_tf32(-x1 * s + x2 * c));
    }
    {
        g_v[dst + i]      = __uint_as_float(cvt_tf32(row[2 * Cq + base + i]));
        g_v[dst + i + 32] = __uint_as_float(cvt_tf32(row[2 * Cq + base + i + 32]));
    }
}

// ---------------------------------------------------------------------------
// Tensor-core flash attention (causal), tf32 mma.sync.
// Block = (qb128, h, b): 128 q rows, 256 threads (8 warps x 16 rows).
// kv tiles of 64 keys, double-buffered cp.async.
// smem floats: Ks[2][4096] swizzled | Vs[2][4608] stride 72 | Ps[8192] swizzled
// ---------------------------------------------------------------------------
#define ATTN2_SMEM_BYTES 102400

__device__ __forceinline__ void load_kv_tile(uint32_t ksm, uint32_t vsm,
                                             const float* kt, const float* vt,
                                             int tid)
{
    int s = tid >> 2, c0 = tid & 3;
#pragma unroll
    for (int i = 0; i < 4; ++i) {
        int c = c0 + i * 4;
        asm volatile("cp.async.cg.shared.global [%0], [%1], 16;"
                     :: "r"(ksm + s * 256 + ((c ^ (s & 7)) << 4)),
                        "l"(kt + s * 64 + c * 4) : "memory");
        asm volatile("cp.async.cg.shared.global [%0], [%1], 16;"
                     :: "r"(vsm + s * 288 + (c << 4)),
                        "l"(vt + s * 64 + c * 4) : "memory");
    }
    asm volatile("cp.async.commit_group;" ::: "memory");
}

__global__ __launch_bounds__(256) void attn_mma(const float* __restrict__ gq,
                                                const float* __restrict__ gk,
                                                const float* __restrict__ gv,
                                                float* __restrict__ gatt)
{
    extern __shared__ float sm2[];
    float* Ks = sm2;                // [2][4096]
    float* Vs = sm2 + 8192;         // [2][4608], stride 72
    float* Ps = sm2 + 17408;        // [8192] (Q staging, then per-warp P)

    const int tid = threadIdx.x;
    const int wid = tid >> 5;
    const int lane = tid & 31;
    const int g = lane >> 2;
    const int r = lane & 3;
    const int qb = (gridDim.x - 1) - blockIdx.x;   // heavy tiles first
    const int h = blockIdx.y;
    const int b = blockIdx.z;

    const float* qp = gq + ((size_t)(b * Hq + h) * Tq + qb * 128) * 64;
    const float* kp = gk + (size_t)(b * Hq + h) * Tq * 64;
    const float* vp = gv + (size_t)(b * Hq + h) * Tq * 64;
    const int nst = 2 * qb + 2;

    const uint32_t ksm = smem_u32(Ks);
    const uint32_t vsm = smem_u32(Vs);

    // prefetch kv tile 0
    load_kv_tile(ksm, vsm, kp, vp, tid);

    // stage Q (128x64) into Ps with swizzle, then lift fragments to registers
#pragma unroll
    for (int i = 0; i < 8; ++i) {
        int idx = tid + i * 256;
        int s = idx >> 4, c = idx & 15;
        float4 v = *(const float4*)(qp + s * 64 + c * 4);
        *(float4*)(Ps + s * 64 + ((c ^ (s & 7)) << 2)) = v;
    }
    __syncthreads();
    uint32_t qf[8][4];
    {
        int q0 = wid * 16 + g;
#pragma unroll
        for (int ks = 0; ks < 8; ++ks) {
            qf[ks][0] = __float_as_uint(Ps[swz(q0, ks * 8 + r)]);
            qf[ks][1] = __float_as_uint(Ps[swz(q0 + 8, ks * 8 + r)]);
            qf[ks][2] = __float_as_uint(Ps[swz(q0, ks * 8 + r + 4)]);
            qf[ks][3] = __float_as_uint(Ps[swz(q0 + 8, ks * 8 + r + 4)]);
        }
    }
    __syncthreads();

    // Precomputed swizzle bases (rows of 64 floats):
    uint32_t ikb[8];
#pragma unroll
    for (int nt = 0; nt < 8; ++nt) {
        int row = nt * 8 + g;
        ikb[nt] = row * 64 + ((row & 7) << 2) + r;
    }
    const uint32_t ipa0 = g * 64 + ((g & 7) << 2) + r;
    const uint32_t ipa1 = (g + 8) * 64 + ((g & 7) << 2) + r;
    const uint32_t pw_lo = (((r >> 1) ^ (g & 7)) << 2) + ((2 * r) & 3);
    const uint32_t ipw0 = g * 64 + pw_lo;
    const uint32_t ipw1 = (g + 8) * 64 + pw_lo;

    float m0 = -1e30f, m1 = -1e30f, l0 = 0.0f, l1 = 0.0f;
    float o[8][4];
#pragma unroll
    for (int dt = 0; dt < 8; ++dt)
#pragma unroll
        for (int j = 0; j < 4; ++j) o[dt][j] = 0.0f;

    float* Pw = Ps + wid * 1024;
    const int qlo = qb * 128 + wid * 16;
    const int qr0 = qlo + g;

    for (int st = 0; st < nst; ++st) {
        if (st + 1 < nst) {
            load_kv_tile(ksm + ((st + 1) & 1) * 16384, vsm + ((st + 1) & 1) * 18432,
                         kp + (size_t)(st + 1) * 4096, vp + (size_t)(st + 1) * 4096, tid);
            asm volatile("cp.async.wait_group 1;" ::: "memory");
        } else {
            asm volatile("cp.async.wait_group 0;" ::: "memory");
        }
        __syncthreads();

        const int collo = st * 64;
        if (collo <= qlo + 15) {                 // warp not fully masked
            const float* kb = Ks + (st & 1) * 4096;
            const float* vb = Vs + (st & 1) * 4608;

            // S = Q K^T
            float s4[8][4];
#pragma unroll
            for (int nt = 0; nt < 8; ++nt)
#pragma unroll
                for (int j = 0; j < 4; ++j) s4[nt][j] = 0.0f;
#pragma unroll
            for (int ks = 0; ks < 8; ++ks) {
                const uint32_t x0 = ks * 8, x1 = ks * 8 + 4;
#pragma unroll
                for (int nt = 0; nt < 8; ++nt) {
                    uint32_t bk[2];
                    bk[0] = __float_as_uint(kb[ikb[nt] ^ x0]);
                    bk[1] = __float_as_uint(kb[ikb[nt] ^ x1]);
                    mma_tf32(s4[nt], qf[ks], bk);
                }
            }

            const bool diag = (collo + 63 > qlo);
#pragma unroll
            for (int nt = 0; nt < 8; ++nt) {
                s4[nt][0] *= 0.125f; s4[nt][1] *= 0.125f;
                s4[nt][2] *= 0.125f; s4[nt][3] *= 0.125f;
                if (diag) {
                    int c0 = collo + nt * 8 + 2 * r;
                    if (c0     > qr0)     s4[nt][0] = -1e30f;
                    if (c0 + 1 > qr0)     s4[nt][1] = -1e30f;
                    if (c0     > qr0 + 8) s4[nt][2] = -1e30f;
                    if (c0 + 1 > qr0 + 8) s4[nt][3] = -1e30f;
                }
            }

            // online softmax (rows qr0 and qr0+8)
            float mx0 = -1e30f, mx1 = -1e30f;
#pragma unroll
            for (int nt = 0; nt < 8; ++nt) {
                mx0 = fmaxf(mx0, fmaxf(s4[nt][0], s4[nt][1]));
                mx1 = fmaxf(mx1, fmaxf(s4[nt][2], s4[nt][3]));
            }
            mx0 = fmaxf(mx0, __shfl_xor_sync(0xffffffffu, mx0, 1));
            mx0 = fmaxf(mx0, __shfl_xor_sync(0xffffffffu, mx0, 2));
            mx1 = fmaxf(mx1, __shfl_xor_sync(0xffffffffu, mx1, 1));
            mx1 = fmaxf(mx1, __shfl_xor_sync(0xffffffffu, mx1, 2));

            float mn0 = fmaxf(m0, mx0), mn1 = fmaxf(m1, mx1);
            float cr0 = __expf(m0 - mn0), cr1 = __expf(m1 - mn1);
            m0 = mn0; m1 = mn1;

            float sum0 = 0.0f, sum1 = 0.0f;
#pragma unroll
            for (int nt = 0; nt < 8; ++nt) {
                float p00 = __expf(s4[nt][0] - m0);
                float p01 = __expf(s4[nt][1] - m0);
                float p10 = __expf(s4[nt][2] - m1);
                float p11 = __expf(s4[nt][3] - m1);
                sum0 += p00 + p01;
                sum1 += p10 + p11;
                *(float2*)(Pw + (ipw0 ^ (uint32_t)(nt * 8))) =
                    make_float2(__uint_as_float(cvt_tf32(p00)),
                                __uint_as_float(cvt_tf32(p01)));
                *(float2*)(Pw + (ipw1 ^ (uint32_t)(nt * 8))) =
                    make_float2(__uint_as_float(cvt_tf32(p10)),
                                __uint_as_float(cvt_tf32(p11)));
            }
            sum0 += __shfl_xor_sync(0xffffffffu, sum0, 1);
            sum0 += __shfl_xor_sync(0xffffffffu, sum0, 2);
            sum1 += __shfl_xor_sync(0xffffffffu, sum1, 1);
            sum1 += __shfl_xor_sync(0xffffffffu, sum1, 2);
            l0 = l0 * cr0 + sum0;
            l1 = l1 * cr1 + sum1;

#pragma unroll
            for (int dt = 0; dt < 8; ++dt) {
                o[dt][0] *= cr0; o[dt][1] *= cr0;
                o[dt][2] *= cr1; o[dt][3] *= cr1;
            }
            __syncwarp();

            // O += P V
#pragma unroll
            for (int ks = 0; ks < 8; ++ks) {
                const uint32_t x0 = ks * 8, x1 = ks * 8 + 4;
                uint32_t pa[4];
                pa[0] = __float_as_uint(Pw[ipa0 ^ x0]);
                pa[1] = __float_as_uint(Pw[ipa1 ^ x0]);
                pa[2] = __float_as_uint(Pw[ipa0 ^ x1]);
                pa[3] = __float_as_uint(Pw[ipa1 ^ x1]);
#pragma unroll
                for (int dt = 0; dt < 8; ++dt) {
                    uint32_t bv[2];
                    bv[0] = __float_as_uint(vb[(ks * 8 + r) * 72 + dt * 8 + g]);
                    bv[1] = __float_as_uint(vb[(ks * 8 + r + 4) * 72 + dt * 8 + g]);
                    mma_tf32(o[dt], pa, bv);
                }
            }
        }
        __syncthreads();   // protect K/V buffers & Ps before next iteration
    }

    // finalize: write tf32-rounded output (A operand of proj GEMM)
    float li0 = 1.0f / l0, li1 = 1.0f / l1;
    int t0 = qb * 128 + wid * 16 + g;
    float* ob = gatt + ((size_t)b * Tq + t0) * Cq + h * 64;
#pragma unroll
    for (int dt = 0; dt < 8; ++dt) {
        int cc = dt * 8 + 2 * r;
        *(float2*)(ob + cc) =
            make_float2(__uint_as_float(cvt_tf32(o[dt][0] * li0)),
                        __uint_as_float(cvt_tf32(o[dt][1] * li0)));
        *(float2*)(ob + 8 * Cq + cc) =
            make_float2(__uint_as_float(cvt_tf32(o[dt][2] * li1)),
                        __uint_as_float(cvt_tf32(o[dt][3] * li1)));
    }
}

// ---------------------------------------------------------------------------
// Launch
// ---------------------------------------------------------------------------
extern "C" void kernel_launch(void* const* d_in, const int* in_sizes, int n_in,
                              void* d_out, int out_size)
{
    const float* x      = (const float*)d_in[0];
    const float* w_qkv  = (const float*)d_in[1];
    const float* w_proj = (const float*)d_in[2];
    float* out = (float*)d_out;

    float *qkv, *q, *k, *v, *att, *xr, *wqr, *wpr;
    cudaGetSymbolAddress((void**)&qkv, g_qkv);
    cudaGetSymbolAddress((void**)&q, g_q);
    cudaGetSymbolAddress((void**)&k, g_k);
    cudaGetSymbolAddress((void**)&v, g_v);
    cudaGetSymbolAddress((void**)&att, g_att);
    cudaGetSymbolAddress((void**)&xr, g_xr);
    cudaGetSymbolAddress((void**)&wqr, g_wqkv_r);
    cudaGetSymbolAddress((void**)&wpr, g_wproj_r);

    const int M = Bq * Tq;  // 8192

    cudaFuncSetAttribute(gemm_tf32, cudaFuncAttributeMaxDynamicSharedMemorySize,
                         GEMM_SMEM_BYTES);
    cudaFuncSetAttribute(attn_mma, cudaFuncAttributeMaxDynamicSharedMemorySize,
                         ATTN2_SMEM_BYTES);

    // 0. tf32-round GEMM operands
    round_tf32_k<<<(M * Cq / 4 + 255) / 256, 256>>>(x, xr, M * Cq / 4);
    round_tf32_k<<<(3 * Cq * Cq / 4 + 255) / 256, 256>>>(w_qkv, wqr, 3 * Cq * Cq / 4);
    round_tf32_k<<<(Cq * Cq / 4 + 255) / 256, 256>>>(w_proj, wpr, Cq * Cq / 4);

    // 1. qkv = x @ w_qkv^T
    gemm_tf32<<<dim3((3 * Cq) / 128, M / 128), 128, GEMM_SMEM_BYTES>>>(
        xr, wqr, qkv, M, 3 * Cq, Cq);

    // 2. RoPE + scatter (tf32-rounded q/k/v)
    rope_scatter<<<(Bq * Tq * Hq * 32) / 256, 256>>>();

    // 3. Tensor-core causal flash attention
    attn_mma<<<dim3(Tq / 128, Hq, Bq), 256, ATTN2_SMEM_BYTES>>>(q, k, v, att);

    // 4. out = att @ w_proj^T
    gemm_tf32<<<dim3(Cq / 128, M / 128), 128, GEMM_SMEM_BYTES>>>(
        att, wpr, out, M, Cq, Cq);
}